// round 12
// baseline (speedup 1.0000x reference)
#include <cuda_runtime.h>
#include <cuda_bf16.h>
#include <cstdint>

// Problem constants: B=32, S=2048, D=256, K=2048
#define NPOS   65536
#define DIMH   256
#define DIMF   512
#define KCB    2048

// ---------------------------------------------------------------------------
// Device scratch (static; no cudaMalloc anywhere)
__device__ __nv_bfloat16 g_zhi[(size_t)NPOS * DIMF];   // 64 MB
__device__ __nv_bfloat16 g_zlo[(size_t)NPOS * DIMF];   // 64 MB
__device__ __nv_bfloat16 g_chi[(size_t)KCB * DIMF];    // 2 MB
__device__ __nv_bfloat16 g_clo[(size_t)KCB * DIMF];    // 2 MB
__device__ float  g_cnorm[KCB];
__device__ float  g_table[(size_t)KCB * KCB];          // 16 MB
__device__ int    g_min_idx[NPOS];
__device__ double g_loss_sum;

// ---------------------------------------------------------------------------
__global__ void cnorm_split_kernel(const float* __restrict__ codebook) {
    const int k = blockIdx.x;
    const int t = threadIdx.x;   // 128 threads, each owns 4 elems
    float4 v = *reinterpret_cast<const float4*>(codebook + (size_t)k * DIMF + t * 4);
    float s = v.x * v.x + v.y * v.y + v.z * v.z + v.w * v.w;

    float e[4] = {v.x, v.y, v.z, v.w};
    __nv_bfloat16 hi[4], lo[4];
#pragma unroll
    for (int i = 0; i < 4; ++i) {
        hi[i] = __float2bfloat16(e[i]);
        lo[i] = __float2bfloat16(e[i] - __bfloat162float(hi[i]));
    }
    size_t base = (size_t)k * DIMF + t * 4;
    *reinterpret_cast<__nv_bfloat162*>(g_chi + base)     = __nv_bfloat162(hi[0], hi[1]);
    *reinterpret_cast<__nv_bfloat162*>(g_chi + base + 2) = __nv_bfloat162(hi[2], hi[3]);
    *reinterpret_cast<__nv_bfloat162*>(g_clo + base)     = __nv_bfloat162(lo[0], lo[1]);
    *reinterpret_cast<__nv_bfloat162*>(g_clo + base + 2) = __nv_bfloat162(lo[2], lo[3]);

    __shared__ float red[128];
    red[t] = s;
    __syncthreads();
    for (int st = 64; st > 0; st >>= 1) {
        if (t < st) red[t] += red[t + st];
        __syncthreads();
    }
    if (t == 0) g_cnorm[k] = red[0];
}

// ---------------------------------------------------------------------------
// Split z (concat real/imag) into bf16 hi/lo. 8 elems/thread, 16B stores.
__global__ void convert_z_kernel(const float* __restrict__ z_real,
                                 const float* __restrict__ z_imag) {
    size_t e8 = (size_t)blockIdx.x * blockDim.x + threadIdx.x;
    size_t e  = e8 * 8;                      // element index in (NPOS, 512)
    int row = (int)(e >> 9);
    int c   = (int)(e & 511);                // multiple of 8; never crosses 256
    const float* src = (c < DIMH)
        ? (z_real + (size_t)row * DIMH + c)
        : (z_imag + (size_t)row * DIMH + (c - DIMH));
    float4 v0 = *reinterpret_cast<const float4*>(src);
    float4 v1 = *reinterpret_cast<const float4*>(src + 4);
    float el[8] = {v0.x, v0.y, v0.z, v0.w, v1.x, v1.y, v1.z, v1.w};
    __nv_bfloat16 hi[8], lo[8];
#pragma unroll
    for (int i = 0; i < 8; ++i) {
        hi[i] = __float2bfloat16(el[i]);
        lo[i] = __float2bfloat16(el[i] - __bfloat162float(hi[i]));
    }
    union { __nv_bfloat162 h2[4]; uint4 u; } ph, pl;
#pragma unroll
    for (int i = 0; i < 4; ++i) {
        ph.h2[i] = __nv_bfloat162(hi[2 * i], hi[2 * i + 1]);
        pl.h2[i] = __nv_bfloat162(lo[2 * i], lo[2 * i + 1]);
    }
    *reinterpret_cast<uint4*>(g_zhi + e) = ph.u;
    *reinterpret_cast<uint4*>(g_zlo + e) = pl.u;
}

// ---------------------------------------------------------------------------
// table[p*K + k] = cnorm[k] - 0.5 * sigmoid(adjacency[p][k]); 4 elems/thread.
// Also zeroes the loss accumulator (always runs before gather_loss).
__global__ void table_kernel(const float* __restrict__ adjacency) {
    size_t i4 = (size_t)blockIdx.x * blockDim.x + threadIdx.x;
    if (i4 == 0) g_loss_sum = 0.0;
    size_t base = i4 * 4;
    int k = (int)(base & (KCB - 1));         // multiple of 4; stays in-row
    float4 a = *reinterpret_cast<const float4*>(adjacency + base);
    float4 r;
    r.x = g_cnorm[k + 0] - 0.5f * (1.0f / (1.0f + __expf(-a.x)));
    r.y = g_cnorm[k + 1] - 0.5f * (1.0f / (1.0f + __expf(-a.y)));
    r.z = g_cnorm[k + 2] - 0.5f * (1.0f / (1.0f + __expf(-a.z)));
    r.w = g_cnorm[k + 3] - 0.5f * (1.0f / (1.0f + __expf(-a.w)));
    *reinterpret_cast<float4*>(g_table + base) = r;
}

// ---------------------------------------------------------------------------
// PTX helpers
__device__ __forceinline__ void cp_async16(uint32_t smem, const void* gmem) {
    asm volatile("cp.async.cg.shared.global [%0], [%1], 16;\n"
                 :: "r"(smem), "l"(gmem));
}
__device__ __forceinline__ void cp_commit() {
    asm volatile("cp.async.commit_group;\n");
}
__device__ __forceinline__ void cp_wait1() {
    asm volatile("cp.async.wait_group 1;\n" ::: "memory");
}
__device__ __forceinline__ void cp_wait0() {
    asm volatile("cp.async.wait_group 0;\n" ::: "memory");
}
__device__ __forceinline__ void ldsm4(uint32_t& r0, uint32_t& r1, uint32_t& r2,
                                      uint32_t& r3, uint32_t addr) {
    asm volatile("ldmatrix.sync.aligned.m8n8.x4.shared.b16 {%0,%1,%2,%3}, [%4];\n"
                 : "=r"(r0), "=r"(r1), "=r"(r2), "=r"(r3) : "r"(addr));
}

#define MMA_BF16(C, A0, A1, A2, A3, B0, B1)                                   \
    asm volatile(                                                             \
        "mma.sync.aligned.m16n8k16.row.col.f32.bf16.bf16.f32 "                \
        "{%0,%1,%2,%3}, {%4,%5,%6,%7}, {%8,%9}, {%0,%1,%2,%3};\n"             \
        : "+f"((C)[0]), "+f"((C)[1]), "+f"((C)[2]), "+f"((C)[3])              \
        : "r"(A0), "r"(A1), "r"(A2), "r"(A3), "r"(B0), "r"(B1))

// SW64 swizzle for 64-byte rows: XOR bits [5:4] with bits [8:7]
__device__ __forceinline__ uint32_t sw64(uint32_t off) {
    return off ^ ((off >> 3) & 0x30);
}

// ---------------------------------------------------------------------------
// Fused split-bf16 tensor-core distance GEMM + argmin.
// Block: 128 rows x (2048 cols looped in 64-col passes). 8 warps, warp tile
// 32x32 -> 32 accumulator regs/thread, so THREE CTAs fit per SM (24 warps;
// R10 profile: tensor=63.6%, occ=22% -> occupancy bound at 2 CTAs/SM).
// K=512 in 16 stages of 32, 3-stage cp.async ring, one sync/stage.
// k16=1 addresses derived from k16=0 by XOR 32 (sw64(x+32) == sw64(x)^32
// when bit 5 of the pre-swizzle offset is clear — ADD here is WRONG: it can
// carry into the row bits and walk off the end of smem, which is exactly the
// R11 crash).
#define KT       32
#define NSTAGE   3
#define A_B      (128 * 64)              // 8 KB per A matrix tile (128 x 32)
#define B_B      (64 * 64)               // 4 KB per B matrix tile (64 x 32)
#define STAGE_B  (2 * A_B + 2 * B_B)     // 24 KB
#define SMEM_TOT (NSTAGE * STAGE_B)      // 72 KB -> 3 CTAs in 228 KB

__device__ __forceinline__ void issue_stage(int row0, int n0, int k0,
                                            uint32_t sb) {
    const int tid = threadIdx.x;
    // A: zhi, zlo (128 rows x 32 cols = 512 16B-chunks each; 2 per thread)
#pragma unroll
    for (int i = 0; i < 2; ++i) {
        const int c   = i * 256 + tid;
        const int row = c >> 2, cc = c & 3;
        const uint32_t so = sw64((uint32_t)(row * 64 + cc * 16));
        const size_t ga = (size_t)(row0 + row) * DIMF + k0 + cc * 8;
        cp_async16(sb + 0 * A_B + so, g_zhi + ga);
        cp_async16(sb + 1 * A_B + so, g_zlo + ga);
    }
    // B: chi, clo (64 rows x 32 cols = 256 chunks each; 1 per thread)
    {
        const int row = tid >> 2, cc = tid & 3;
        const uint32_t so = sw64((uint32_t)(row * 64 + cc * 16));
        const size_t gb = (size_t)(n0 + row) * DIMF + k0 + cc * 8;
        cp_async16(sb + 2 * A_B + so,       g_chi + gb);
        cp_async16(sb + 2 * A_B + B_B + so, g_clo + gb);
    }
}

__global__ void __launch_bounds__(256, 3)
vq_argmin_mma_kernel(const int* __restrict__ prev_idx,
                     float*     __restrict__ idx_f32_out)
{
    extern __shared__ __align__(128) uint8_t dsm[];
    const uint32_t tiles = (uint32_t)__cvta_generic_to_shared(dsm);

    const int tid    = threadIdx.x;
    const int lane   = tid & 31;
    const int warp   = tid >> 5;
    const int warp_m = warp & 3;      // 4 warps along rows (32 each)
    const int warp_n = warp >> 2;     // 2 warps along cols (32 each)
    const int row0   = blockIdx.x * 128;

    // ldmatrix byte offsets for k16=0; k16=1 is obtained by XOR 32 (see above)
    uint32_t a_off[2], b_off[2];
#pragma unroll
    for (int im = 0; im < 2; ++im)
        a_off[im] = sw64((uint32_t)(
            (warp_m * 32 + im * 16 + (lane & 15)) * 64 + (lane >> 4) * 16));
#pragma unroll
    for (int jp = 0; jp < 2; ++jp)
        b_off[jp] = sw64((uint32_t)(
            (warp_n * 32 + jp * 16 + (lane >> 4) * 8 + (lane & 7)) * 64 +
            ((lane & 8) ? 16 : 0)));

    // prev-symbol rows owned by this thread (pass-invariant)
    const int q = lane >> 2;
    int prevA[2], prevB[2];
#pragma unroll
    for (int im = 0; im < 2; ++im) {
        prevA[im] = prev_idx[row0 + warp_m * 32 + im * 16 + q];
        prevB[im] = prev_idx[row0 + warp_m * 32 + im * 16 + q + 8];
    }
    const int j2 = (lane & 3) * 2;

    float bv[4];
    int   bi[4];
#pragma unroll
    for (int s = 0; s < 4; ++s) { bv[s] = 3.4e38f; bi[s] = 0; }

    for (int nt = 0; nt < KCB / 64; ++nt) {
        const int n0 = nt * 64;

        float acc[2][4][4];
#pragma unroll
        for (int im = 0; im < 2; ++im)
#pragma unroll
            for (int jn = 0; jn < 4; ++jn)
#pragma unroll
                for (int r = 0; r < 4; ++r) acc[im][jn][r] = 0.0f;

        // prologue: 2 stages in flight
        issue_stage(row0, n0, 0, tiles);
        cp_commit();
        issue_stage(row0, n0, KT, tiles + STAGE_B);
        cp_commit();

        for (int kt = 0; kt < DIMF / KT; ++kt) {
            if (kt == DIMF / KT - 1) cp_wait0(); else cp_wait1();
            __syncthreads();
            if (kt + 2 < DIMF / KT) {
                issue_stage(row0, n0, (kt + 2) * KT,
                            tiles + (uint32_t)((kt + 2) % NSTAGE) * STAGE_B);
                cp_commit();
            }

            const uint32_t sb = tiles + (uint32_t)(kt % NSTAGE) * STAGE_B;
#pragma unroll
            for (int k16 = 0; k16 < 2; ++k16) {
                const uint32_t kx = (uint32_t)(k16 * 32);   // XOR, not add!
                uint32_t ah[2][4], al[2][4];
#pragma unroll
                for (int im = 0; im < 2; ++im) {
                    ldsm4(ah[im][0], ah[im][1], ah[im][2], ah[im][3],
                          sb + 0 * A_B + (a_off[im] ^ kx));
                    ldsm4(al[im][0], al[im][1], al[im][2], al[im][3],
                          sb + 1 * A_B + (a_off[im] ^ kx));
                }
#pragma unroll
                for (int jp = 0; jp < 2; ++jp) {
                    uint32_t bh0, bh1, bh2, bh3, bl0, bl1, bl2, bl3;
                    ldsm4(bh0, bh1, bh2, bh3,
                          sb + 2 * A_B + (b_off[jp] ^ kx));
                    ldsm4(bl0, bl1, bl2, bl3,
                          sb + 2 * A_B + B_B + (b_off[jp] ^ kx));
#pragma unroll
                    for (int im = 0; im < 2; ++im) {
                        float* c0 = acc[im][jp * 2];
                        float* c1 = acc[im][jp * 2 + 1];
                        MMA_BF16(c0, ah[im][0], ah[im][1], ah[im][2], ah[im][3], bh0, bh1);
                        MMA_BF16(c0, ah[im][0], ah[im][1], ah[im][2], ah[im][3], bl0, bl1);
                        MMA_BF16(c0, al[im][0], al[im][1], al[im][2], al[im][3], bh0, bh1);
                        MMA_BF16(c1, ah[im][0], ah[im][1], ah[im][2], ah[im][3], bh2, bh3);
                        MMA_BF16(c1, ah[im][0], ah[im][1], ah[im][2], ah[im][3], bl2, bl3);
                        MMA_BF16(c1, al[im][0], al[im][1], al[im][2], al[im][3], bh2, bh3);
                    }
                }
            }
        }
        // all warps done reading this pass's buffers before next prologue
        __syncthreads();

        // Epilogue: fold bias table, update running argmin
        const int ncol0 = n0 + warp_n * 32 + j2;
#pragma unroll
        for (int im = 0; im < 2; ++im) {
            const float* tA = g_table + (size_t)prevA[im] * KCB + ncol0;
            const float* tB = g_table + (size_t)prevB[im] * KCB + ncol0;
#pragma unroll
            for (int jn = 0; jn < 4; ++jn) {
                float2 ta = *reinterpret_cast<const float2*>(tA + jn * 8);
                float2 tb = *reinterpret_cast<const float2*>(tB + jn * 8);
                const int col = ncol0 + jn * 8;
                float s0 = ta.x - 2.0f * acc[im][jn][0];
                float s1 = ta.y - 2.0f * acc[im][jn][1];
                float s2 = tb.x - 2.0f * acc[im][jn][2];
                float s3 = tb.y - 2.0f * acc[im][jn][3];
                const int sl0 = im * 2, sl1 = im * 2 + 1;
                if (s0 < bv[sl0]) { bv[sl0] = s0; bi[sl0] = col; }
                if (s1 < bv[sl0]) { bv[sl0] = s1; bi[sl0] = col + 1; }
                if (s2 < bv[sl1]) { bv[sl1] = s2; bi[sl1] = col; }
                if (s3 < bv[sl1]) { bv[sl1] = s3; bi[sl1] = col + 1; }
            }
        }
    }

    // Quad (4-lane) reduction: lanes sharing t/4 own the same row
#pragma unroll
    for (int s = 0; s < 4; ++s) {
#pragma unroll
        for (int d = 1; d < 4; d <<= 1) {
            float ov = __shfl_xor_sync(0xffffffffu, bv[s], d);
            int   oi = __shfl_xor_sync(0xffffffffu, bi[s], d);
            if (ov < bv[s] || (ov == bv[s] && oi < bi[s])) { bv[s] = ov; bi[s] = oi; }
        }
    }

    // Cross-warp (warp_n 0 vs 1) reduction via smem (reuse tile buffer)
    __syncthreads();
    float* sv = reinterpret_cast<float*>(dsm);            // [128][2]
    int*   si = reinterpret_cast<int*>(sv + 256);         // [128][2]
    if ((lane & 3) == 0) {
#pragma unroll
        for (int s = 0; s < 4; ++s) {
            const int im = s >> 1, h = s & 1;
            const int rl = warp_m * 32 + im * 16 + h * 8 + q;
            sv[rl * 2 + warp_n] = bv[s];
            si[rl * 2 + warp_n] = bi[s];
        }
    }
    __syncthreads();
    if (tid < 128) {
        float v0 = sv[tid * 2], v1 = sv[tid * 2 + 1];
        int   i0 = si[tid * 2], i1 = si[tid * 2 + 1];
        int best;
        if (v1 < v0 || (v1 == v0 && i1 < i0)) best = i1; else best = i0;
        g_min_idx[row0 + tid]   = best;
        idx_f32_out[row0 + tid] = (float)best;
    }
}

// ---------------------------------------------------------------------------
__global__ void gather_loss_kernel(const float* __restrict__ z_real,
                                   const float* __restrict__ z_imag,
                                   const float* __restrict__ codebook,
                                   float* __restrict__ out_real,
                                   float* __restrict__ out_imag)
{
    const int t = threadIdx.x;
    float local = 0.0f;
    for (int p = blockIdx.x; p < NPOS; p += gridDim.x) {
        const int idx = g_min_idx[p];
        float4 c4 = *reinterpret_cast<const float4*>(
            codebook + (size_t)idx * DIMF + t * 4);
        float4 z4;
        if (t < 64)
            z4 = *reinterpret_cast<const float4*>(z_real + (size_t)p * DIMH + t * 4);
        else
            z4 = *reinterpret_cast<const float4*>(z_imag + (size_t)p * DIMH + (t - 64) * 4);
        float dx = c4.x - z4.x, dy = c4.y - z4.y;
        float dz = c4.z - z4.z, dw = c4.w - z4.w;
        local += dx * dx + dy * dy + dz * dz + dw * dw;
        if (t < 64)
            *reinterpret_cast<float4*>(out_real + (size_t)p * DIMH + t * 4) = c4;
        else
            *reinterpret_cast<float4*>(out_imag + (size_t)p * DIMH + (t - 64) * 4) = c4;
    }
    __shared__ float red[128];
    red[t] = local;
    __syncthreads();
    for (int st = 64; st > 0; st >>= 1) {
        if (t < st) red[t] += red[t + st];
        __syncthreads();
    }
    if (t == 0) atomicAdd(&g_loss_sum, (double)red[0]);
}

// ---------------------------------------------------------------------------
__global__ void finalize_kernel(float* __restrict__ out_loss) {
    out_loss[0] = (float)(1.25 * g_loss_sum / (double)((size_t)NPOS * DIMF));
}

// ---------------------------------------------------------------------------
extern "C" void kernel_launch(void* const* d_in, const int* in_sizes, int n_in,
                              void* d_out, int out_size)
{
    const float* z_real    = (const float*)d_in[0];
    const float* z_imag    = (const float*)d_in[1];
    const int*   prev_idx  = (const int*)  d_in[2];
    const float* codebook  = (const float*)d_in[3];
    const float* adjacency = (const float*)d_in[4];

    float* out      = (float*)d_out;
    float* out_real = out;
    float* out_imag = out + (size_t)NPOS * DIMH;
    float* out_loss = out + 2 * (size_t)NPOS * DIMH;
    float* out_idx  = out_loss + 1;

    cudaFuncSetAttribute(vq_argmin_mma_kernel,
                         cudaFuncAttributeMaxDynamicSharedMemorySize, SMEM_TOT);

    cnorm_split_kernel<<<KCB, 128>>>(codebook);
    convert_z_kernel<<<(NPOS * (DIMF / 8)) / 256, 256>>>(z_real, z_imag);
    table_kernel<<<((size_t)KCB * KCB / 4) / 256, 256>>>(adjacency);
    vq_argmin_mma_kernel<<<NPOS / 128, 256, SMEM_TOT>>>(prev_idx, out_idx);
    gather_loss_kernel<<<2048, 128>>>(z_real, z_imag, codebook, out_real, out_imag);
    finalize_kernel<<<1, 1>>>(out_loss);
}

// round 13
// speedup vs baseline: 1.1827x; 1.1827x over previous
#include <cuda_runtime.h>
#include <cuda_bf16.h>
#include <cstdint>

// Problem constants: B=32, S=2048, D=256, K=2048
#define NPOS   65536
#define DIMH   256
#define DIMF   512
#define KCB    2048

// ---------------------------------------------------------------------------
// Device scratch (static; no cudaMalloc anywhere)
__device__ __nv_bfloat16 g_zhi[(size_t)NPOS * DIMF];   // 64 MB
__device__ __nv_bfloat16 g_zlo[(size_t)NPOS * DIMF];   // 64 MB
__device__ __nv_bfloat16 g_chi[(size_t)KCB * DIMF];    // 2 MB
__device__ __nv_bfloat16 g_clo[(size_t)KCB * DIMF];    // 2 MB
__device__ float  g_cnorm[KCB];
__device__ float  g_table[(size_t)KCB * KCB];          // 16 MB
__device__ int    g_min_idx[NPOS];
__device__ double g_loss_sum;

// ---------------------------------------------------------------------------
__global__ void cnorm_split_kernel(const float* __restrict__ codebook) {
    const int k = blockIdx.x;
    const int t = threadIdx.x;   // 128 threads, each owns 4 elems
    float4 v = *reinterpret_cast<const float4*>(codebook + (size_t)k * DIMF + t * 4);
    float s = v.x * v.x + v.y * v.y + v.z * v.z + v.w * v.w;

    float e[4] = {v.x, v.y, v.z, v.w};
    __nv_bfloat16 hi[4], lo[4];
#pragma unroll
    for (int i = 0; i < 4; ++i) {
        hi[i] = __float2bfloat16(e[i]);
        lo[i] = __float2bfloat16(e[i] - __bfloat162float(hi[i]));
    }
    size_t base = (size_t)k * DIMF + t * 4;
    *reinterpret_cast<__nv_bfloat162*>(g_chi + base)     = __nv_bfloat162(hi[0], hi[1]);
    *reinterpret_cast<__nv_bfloat162*>(g_chi + base + 2) = __nv_bfloat162(hi[2], hi[3]);
    *reinterpret_cast<__nv_bfloat162*>(g_clo + base)     = __nv_bfloat162(lo[0], lo[1]);
    *reinterpret_cast<__nv_bfloat162*>(g_clo + base + 2) = __nv_bfloat162(lo[2], lo[3]);

    __shared__ float red[128];
    red[t] = s;
    __syncthreads();
    for (int st = 64; st > 0; st >>= 1) {
        if (t < st) red[t] += red[t + st];
        __syncthreads();
    }
    if (t == 0) g_cnorm[k] = red[0];
}

// ---------------------------------------------------------------------------
// Split z (concat real/imag) into bf16 hi/lo. 8 elems/thread, 16B stores.
__global__ void convert_z_kernel(const float* __restrict__ z_real,
                                 const float* __restrict__ z_imag) {
    size_t e8 = (size_t)blockIdx.x * blockDim.x + threadIdx.x;
    size_t e  = e8 * 8;                      // element index in (NPOS, 512)
    int row = (int)(e >> 9);
    int c   = (int)(e & 511);                // multiple of 8; never crosses 256
    const float* src = (c < DIMH)
        ? (z_real + (size_t)row * DIMH + c)
        : (z_imag + (size_t)row * DIMH + (c - DIMH));
    float4 v0 = *reinterpret_cast<const float4*>(src);
    float4 v1 = *reinterpret_cast<const float4*>(src + 4);
    float el[8] = {v0.x, v0.y, v0.z, v0.w, v1.x, v1.y, v1.z, v1.w};
    __nv_bfloat16 hi[8], lo[8];
#pragma unroll
    for (int i = 0; i < 8; ++i) {
        hi[i] = __float2bfloat16(el[i]);
        lo[i] = __float2bfloat16(el[i] - __bfloat162float(hi[i]));
    }
    union { __nv_bfloat162 h2[4]; uint4 u; } ph, pl;
#pragma unroll
    for (int i = 0; i < 4; ++i) {
        ph.h2[i] = __nv_bfloat162(hi[2 * i], hi[2 * i + 1]);
        pl.h2[i] = __nv_bfloat162(lo[2 * i], lo[2 * i + 1]);
    }
    *reinterpret_cast<uint4*>(g_zhi + e) = ph.u;
    *reinterpret_cast<uint4*>(g_zlo + e) = pl.u;
}

// ---------------------------------------------------------------------------
// table[p*K + k] = cnorm[k] - 0.5 * sigmoid(adjacency[p][k]); 4 elems/thread.
// Also zeroes the loss accumulator (always runs before gather_loss).
__global__ void table_kernel(const float* __restrict__ adjacency) {
    size_t i4 = (size_t)blockIdx.x * blockDim.x + threadIdx.x;
    if (i4 == 0) g_loss_sum = 0.0;
    size_t base = i4 * 4;
    int k = (int)(base & (KCB - 1));         // multiple of 4; stays in-row
    float4 a = *reinterpret_cast<const float4*>(adjacency + base);
    float4 r;
    r.x = g_cnorm[k + 0] - 0.5f * (1.0f / (1.0f + __expf(-a.x)));
    r.y = g_cnorm[k + 1] - 0.5f * (1.0f / (1.0f + __expf(-a.y)));
    r.z = g_cnorm[k + 2] - 0.5f * (1.0f / (1.0f + __expf(-a.z)));
    r.w = g_cnorm[k + 3] - 0.5f * (1.0f / (1.0f + __expf(-a.w)));
    *reinterpret_cast<float4*>(g_table + base) = r;
}

// ---------------------------------------------------------------------------
// PTX helpers
__device__ __forceinline__ void cp_async16(uint32_t smem, const void* gmem) {
    asm volatile("cp.async.cg.shared.global [%0], [%1], 16;\n"
                 :: "r"(smem), "l"(gmem));
}
__device__ __forceinline__ void cp_commit() {
    asm volatile("cp.async.commit_group;\n");
}
__device__ __forceinline__ void cp_wait1() {
    asm volatile("cp.async.wait_group 1;\n" ::: "memory");
}
__device__ __forceinline__ void cp_wait0() {
    asm volatile("cp.async.wait_group 0;\n" ::: "memory");
}
__device__ __forceinline__ void ldsm4(uint32_t& r0, uint32_t& r1, uint32_t& r2,
                                      uint32_t& r3, uint32_t addr) {
    asm volatile("ldmatrix.sync.aligned.m8n8.x4.shared.b16 {%0,%1,%2,%3}, [%4];\n"
                 : "=r"(r0), "=r"(r1), "=r"(r2), "=r"(r3) : "r"(addr));
}

#define MMA_BF16(C, A0, A1, A2, A3, B0, B1)                                   \
    asm volatile(                                                             \
        "mma.sync.aligned.m16n8k16.row.col.f32.bf16.bf16.f32 "                \
        "{%0,%1,%2,%3}, {%4,%5,%6,%7}, {%8,%9}, {%0,%1,%2,%3};\n"             \
        : "+f"((C)[0]), "+f"((C)[1]), "+f"((C)[2]), "+f"((C)[3])              \
        : "r"(A0), "r"(A1), "r"(A2), "r"(A3), "r"(B0), "r"(B1))

// SW64 swizzle for 64-byte rows: XOR bits [5:4] with bits [8:7]
__device__ __forceinline__ uint32_t sw64(uint32_t off) {
    return off ^ ((off >> 3) & 0x30);
}

// ---------------------------------------------------------------------------
// Fused split-bf16 tensor-core distance GEMM + argmin.
// Block: 64 rows x (2048 cols looped in 128-col passes). 8 warps, warp tile
// 16x64 -> 32 accumulator regs/thread, ~75 regs total => THREE CTAs/SM
// (24 warps). Unlike R12 (which halved the N tile and doubled A's DRAM
// re-read traffic), halving the M tile keeps A traffic IDENTICAL to R10
// (16 column passes); only B (codebook, 4MB, L2-resident) is re-read more.
// K=512 in 16 stages of 32, 3-stage cp.async ring, one sync/stage.
// k16=1 smem addresses derived from k16=0 by XOR 32 (NOT add - carry walks
// off the buffer; that was the R11 crash).
#define KT       32
#define NSTAGE   3
#define A_B      (64 * 64)               // 4 KB per A matrix tile (64 x 32)
#define B_B      (128 * 64)              // 8 KB per B matrix tile (128 x 32)
#define STAGE_B  (2 * A_B + 2 * B_B)     // 24 KB
#define SMEM_TOT (NSTAGE * STAGE_B)      // 72 KB -> 3 CTAs in 228 KB

__device__ __forceinline__ void issue_stage(int row0, int n0, int k0,
                                            uint32_t sb) {
    const int tid = threadIdx.x;
    // A: zhi, zlo (64 rows x 32 cols = 256 16B-chunks each; 1 per thread)
    {
        const int row = tid >> 2, cc = tid & 3;
        const uint32_t so = sw64((uint32_t)(row * 64 + cc * 16));
        const size_t ga = (size_t)(row0 + row) * DIMF + k0 + cc * 8;
        cp_async16(sb + 0 * A_B + so, g_zhi + ga);
        cp_async16(sb + 1 * A_B + so, g_zlo + ga);
    }
    // B: chi, clo (128 rows x 32 cols = 512 chunks each; 2 per thread)
#pragma unroll
    for (int i = 0; i < 2; ++i) {
        const int c   = i * 256 + tid;
        const int row = c >> 2, cc = c & 3;
        const uint32_t so = sw64((uint32_t)(row * 64 + cc * 16));
        const size_t gb = (size_t)(n0 + row) * DIMF + k0 + cc * 8;
        cp_async16(sb + 2 * A_B + so,       g_chi + gb);
        cp_async16(sb + 2 * A_B + B_B + so, g_clo + gb);
    }
}

__global__ void __launch_bounds__(256, 3)
vq_argmin_mma_kernel(const int* __restrict__ prev_idx,
                     float*     __restrict__ idx_f32_out)
{
    extern __shared__ __align__(128) uint8_t dsm[];
    const uint32_t tiles = (uint32_t)__cvta_generic_to_shared(dsm);

    const int tid    = threadIdx.x;
    const int lane   = tid & 31;
    const int warp   = tid >> 5;
    const int warp_m = warp & 3;      // 4 warps along rows (16 each)
    const int warp_n = warp >> 2;     // 2 warps along cols (64 each)
    const int row0   = blockIdx.x * 64;

    // ldmatrix byte offsets for k16=0; k16=1 obtained by XOR 32
    const uint32_t a_off = sw64((uint32_t)(
        (warp_m * 16 + (lane & 15)) * 64 + (lane >> 4) * 16));
    uint32_t b_off[4];
#pragma unroll
    for (int jp = 0; jp < 4; ++jp)
        b_off[jp] = sw64((uint32_t)(
            (warp_n * 64 + jp * 16 + (lane >> 4) * 8 + (lane & 7)) * 64 +
            ((lane & 8) ? 16 : 0)));

    // prev-symbol rows owned by this thread (pass-invariant)
    const int q = lane >> 2;
    const int prevA = prev_idx[row0 + warp_m * 16 + q];
    const int prevB = prev_idx[row0 + warp_m * 16 + q + 8];
    const int j2 = (lane & 3) * 2;

    float bv[2];
    int   bi[2];
#pragma unroll
    for (int s = 0; s < 2; ++s) { bv[s] = 3.4e38f; bi[s] = 0; }

    for (int nt = 0; nt < KCB / 128; ++nt) {
        const int n0 = nt * 128;

        float acc[8][4];
#pragma unroll
        for (int jn = 0; jn < 8; ++jn)
#pragma unroll
            for (int r = 0; r < 4; ++r) acc[jn][r] = 0.0f;

        // prologue: 2 stages in flight
        issue_stage(row0, n0, 0, tiles);
        cp_commit();
        issue_stage(row0, n0, KT, tiles + STAGE_B);
        cp_commit();

        for (int kt = 0; kt < DIMF / KT; ++kt) {
            if (kt == DIMF / KT - 1) cp_wait0(); else cp_wait1();
            __syncthreads();
            if (kt + 2 < DIMF / KT) {
                issue_stage(row0, n0, (kt + 2) * KT,
                            tiles + (uint32_t)((kt + 2) % NSTAGE) * STAGE_B);
                cp_commit();
            }

            const uint32_t sb = tiles + (uint32_t)(kt % NSTAGE) * STAGE_B;
#pragma unroll
            for (int k16 = 0; k16 < 2; ++k16) {
                const uint32_t kx = (uint32_t)(k16 * 32);   // XOR, not add
                uint32_t ah[4], al[4];
                ldsm4(ah[0], ah[1], ah[2], ah[3],
                      sb + 0 * A_B + (a_off ^ kx));
                ldsm4(al[0], al[1], al[2], al[3],
                      sb + 1 * A_B + (a_off ^ kx));
#pragma unroll
                for (int jp = 0; jp < 4; ++jp) {
                    uint32_t bh0, bh1, bh2, bh3, bl0, bl1, bl2, bl3;
                    ldsm4(bh0, bh1, bh2, bh3,
                          sb + 2 * A_B + (b_off[jp] ^ kx));
                    ldsm4(bl0, bl1, bl2, bl3,
                          sb + 2 * A_B + B_B + (b_off[jp] ^ kx));
                    float* c0 = acc[jp * 2];
                    float* c1 = acc[jp * 2 + 1];
                    MMA_BF16(c0, ah[0], ah[1], ah[2], ah[3], bh0, bh1);
                    MMA_BF16(c0, ah[0], ah[1], ah[2], ah[3], bl0, bl1);
                    MMA_BF16(c0, al[0], al[1], al[2], al[3], bh0, bh1);
                    MMA_BF16(c1, ah[0], ah[1], ah[2], ah[3], bh2, bh3);
                    MMA_BF16(c1, ah[0], ah[1], ah[2], ah[3], bl2, bl3);
                    MMA_BF16(c1, al[0], al[1], al[2], al[3], bh2, bh3);
                }
            }
        }
        // all warps done reading this pass's buffers before next prologue
        __syncthreads();

        // Epilogue: fold bias table, update running argmin
        const int ncol0 = n0 + warp_n * 64 + j2;
        const float* tA = g_table + (size_t)prevA * KCB + ncol0;
        const float* tB = g_table + (size_t)prevB * KCB + ncol0;
#pragma unroll
        for (int jn = 0; jn < 8; ++jn) {
            float2 ta = *reinterpret_cast<const float2*>(tA + jn * 8);
            float2 tb = *reinterpret_cast<const float2*>(tB + jn * 8);
            const int col = ncol0 + jn * 8;
            float s0 = ta.x - 2.0f * acc[jn][0];
            float s1 = ta.y - 2.0f * acc[jn][1];
            float s2 = tb.x - 2.0f * acc[jn][2];
            float s3 = tb.y - 2.0f * acc[jn][3];
            if (s0 < bv[0]) { bv[0] = s0; bi[0] = col; }
            if (s1 < bv[0]) { bv[0] = s1; bi[0] = col + 1; }
            if (s2 < bv[1]) { bv[1] = s2; bi[1] = col; }
            if (s3 < bv[1]) { bv[1] = s3; bi[1] = col + 1; }
        }
    }

    // Quad (4-lane) reduction: lanes sharing q own the same rows
#pragma unroll
    for (int s = 0; s < 2; ++s) {
#pragma unroll
        for (int d = 1; d < 4; d <<= 1) {
            float ov = __shfl_xor_sync(0xffffffffu, bv[s], d);
            int   oi = __shfl_xor_sync(0xffffffffu, bi[s], d);
            if (ov < bv[s] || (ov == bv[s] && oi < bi[s])) { bv[s] = ov; bi[s] = oi; }
        }
    }

    // Cross-warp (warp_n 0 vs 1) reduction via smem (reuse tile buffer)
    __syncthreads();
    float* sv = reinterpret_cast<float*>(dsm);            // [64][2]
    int*   si = reinterpret_cast<int*>(sv + 128);         // [64][2]
    if ((lane & 3) == 0) {
#pragma unroll
        for (int s = 0; s < 2; ++s) {
            const int rl = warp_m * 16 + s * 8 + q;
            sv[rl * 2 + warp_n] = bv[s];
            si[rl * 2 + warp_n] = bi[s];
        }
    }
    __syncthreads();
    if (tid < 64) {
        float v0 = sv[tid * 2], v1 = sv[tid * 2 + 1];
        int   i0 = si[tid * 2], i1 = si[tid * 2 + 1];
        int best;
        if (v1 < v0 || (v1 == v0 && i1 < i0)) best = i1; else best = i0;
        g_min_idx[row0 + tid]   = best;
        idx_f32_out[row0 + tid] = (float)best;
    }
}

// ---------------------------------------------------------------------------
__global__ void gather_loss_kernel(const float* __restrict__ z_real,
                                   const float* __restrict__ z_imag,
                                   const float* __restrict__ codebook,
                                   float* __restrict__ out_real,
                                   float* __restrict__ out_imag)
{
    const int t = threadIdx.x;
    float local = 0.0f;
    for (int p = blockIdx.x; p < NPOS; p += gridDim.x) {
        const int idx = g_min_idx[p];
        float4 c4 = *reinterpret_cast<const float4*>(
            codebook + (size_t)idx * DIMF + t * 4);
        float4 z4;
        if (t < 64)
            z4 = *reinterpret_cast<const float4*>(z_real + (size_t)p * DIMH + t * 4);
        else
            z4 = *reinterpret_cast<const float4*>(z_imag + (size_t)p * DIMH + (t - 64) * 4);
        float dx = c4.x - z4.x, dy = c4.y - z4.y;
        float dz = c4.z - z4.z, dw = c4.w - z4.w;
        local += dx * dx + dy * dy + dz * dz + dw * dw;
        if (t < 64)
            *reinterpret_cast<float4*>(out_real + (size_t)p * DIMH + t * 4) = c4;
        else
            *reinterpret_cast<float4*>(out_imag + (size_t)p * DIMH + (t - 64) * 4) = c4;
    }
    __shared__ float red[128];
    red[t] = local;
    __syncthreads();
    for (int st = 64; st > 0; st >>= 1) {
        if (t < st) red[t] += red[t + st];
        __syncthreads();
    }
    if (t == 0) atomicAdd(&g_loss_sum, (double)red[0]);
}

// ---------------------------------------------------------------------------
__global__ void finalize_kernel(float* __restrict__ out_loss) {
    out_loss[0] = (float)(1.25 * g_loss_sum / (double)((size_t)NPOS * DIMF));
}

// ---------------------------------------------------------------------------
extern "C" void kernel_launch(void* const* d_in, const int* in_sizes, int n_in,
                              void* d_out, int out_size)
{
    const float* z_real    = (const float*)d_in[0];
    const float* z_imag    = (const float*)d_in[1];
    const int*   prev_idx  = (const int*)  d_in[2];
    const float* codebook  = (const float*)d_in[3];
    const float* adjacency = (const float*)d_in[4];

    float* out      = (float*)d_out;
    float* out_real = out;
    float* out_imag = out + (size_t)NPOS * DIMH;
    float* out_loss = out + 2 * (size_t)NPOS * DIMH;
    float* out_idx  = out_loss + 1;

    cudaFuncSetAttribute(vq_argmin_mma_kernel,
                         cudaFuncAttributeMaxDynamicSharedMemorySize, SMEM_TOT);

    cnorm_split_kernel<<<KCB, 128>>>(codebook);
    convert_z_kernel<<<(NPOS * (DIMF / 8)) / 256, 256>>>(z_real, z_imag);
    table_kernel<<<((size_t)KCB * KCB / 4) / 256, 256>>>(adjacency);
    vq_argmin_mma_kernel<<<NPOS / 64, 256, SMEM_TOT>>>(prev_idx, out_idx);
    gather_loss_kernel<<<2048, 128>>>(z_real, z_imag, codebook, out_real, out_imag);
    finalize_kernel<<<1, 1>>>(out_loss);
}

// round 14
// speedup vs baseline: 1.1953x; 1.0107x over previous
#include <cuda_runtime.h>
#include <cuda_bf16.h>
#include <cstdint>

// Problem constants: B=32, S=2048, D=256, K=2048
#define NPOS   65536
#define DIMH   256
#define DIMF   512
#define KCB    2048

// ---------------------------------------------------------------------------
// Device scratch (static; no cudaMalloc anywhere)
__device__ __nv_bfloat16 g_zhi[(size_t)NPOS * DIMF];   // 64 MB
__device__ __nv_bfloat16 g_zlo[(size_t)NPOS * DIMF];   // 64 MB
__device__ __nv_bfloat16 g_chi[(size_t)KCB * DIMF];    // 2 MB
__device__ __nv_bfloat16 g_clo[(size_t)KCB * DIMF];    // 2 MB
__device__ float  g_cnorm[KCB];
__device__ float  g_table[(size_t)KCB * KCB];          // 16 MB
__device__ int    g_min_idx[NPOS];
__device__ double g_loss_sum;

// ---------------------------------------------------------------------------
__global__ void cnorm_split_kernel(const float* __restrict__ codebook) {
    const int k = blockIdx.x;
    const int t = threadIdx.x;   // 128 threads, each owns 4 elems
    float4 v = *reinterpret_cast<const float4*>(codebook + (size_t)k * DIMF + t * 4);
    float s = v.x * v.x + v.y * v.y + v.z * v.z + v.w * v.w;

    float e[4] = {v.x, v.y, v.z, v.w};
    __nv_bfloat16 hi[4], lo[4];
#pragma unroll
    for (int i = 0; i < 4; ++i) {
        hi[i] = __float2bfloat16(e[i]);
        lo[i] = __float2bfloat16(e[i] - __bfloat162float(hi[i]));
    }
    size_t base = (size_t)k * DIMF + t * 4;
    *reinterpret_cast<__nv_bfloat162*>(g_chi + base)     = __nv_bfloat162(hi[0], hi[1]);
    *reinterpret_cast<__nv_bfloat162*>(g_chi + base + 2) = __nv_bfloat162(hi[2], hi[3]);
    *reinterpret_cast<__nv_bfloat162*>(g_clo + base)     = __nv_bfloat162(lo[0], lo[1]);
    *reinterpret_cast<__nv_bfloat162*>(g_clo + base + 2) = __nv_bfloat162(lo[2], lo[3]);

    __shared__ float red[128];
    red[t] = s;
    __syncthreads();
    for (int st = 64; st > 0; st >>= 1) {
        if (t < st) red[t] += red[t + st];
        __syncthreads();
    }
    if (t == 0) g_cnorm[k] = red[0];
}

// ---------------------------------------------------------------------------
// Split z (concat real/imag) into bf16 hi/lo. 8 elems/thread, 16B stores.
__global__ void convert_z_kernel(const float* __restrict__ z_real,
                                 const float* __restrict__ z_imag) {
    size_t e8 = (size_t)blockIdx.x * blockDim.x + threadIdx.x;
    size_t e  = e8 * 8;                      // element index in (NPOS, 512)
    int row = (int)(e >> 9);
    int c   = (int)(e & 511);                // multiple of 8; never crosses 256
    const float* src = (c < DIMH)
        ? (z_real + (size_t)row * DIMH + c)
        : (z_imag + (size_t)row * DIMH + (c - DIMH));
    float4 v0 = *reinterpret_cast<const float4*>(src);
    float4 v1 = *reinterpret_cast<const float4*>(src + 4);
    float el[8] = {v0.x, v0.y, v0.z, v0.w, v1.x, v1.y, v1.z, v1.w};
    __nv_bfloat16 hi[8], lo[8];
#pragma unroll
    for (int i = 0; i < 8; ++i) {
        hi[i] = __float2bfloat16(el[i]);
        lo[i] = __float2bfloat16(el[i] - __bfloat162float(hi[i]));
    }
    union { __nv_bfloat162 h2[4]; uint4 u; } ph, pl;
#pragma unroll
    for (int i = 0; i < 4; ++i) {
        ph.h2[i] = __nv_bfloat162(hi[2 * i], hi[2 * i + 1]);
        pl.h2[i] = __nv_bfloat162(lo[2 * i], lo[2 * i + 1]);
    }
    *reinterpret_cast<uint4*>(g_zhi + e) = ph.u;
    *reinterpret_cast<uint4*>(g_zlo + e) = pl.u;
}

// ---------------------------------------------------------------------------
// table[p*K + k] = cnorm[k] - 0.5 * sigmoid(adjacency[p][k]); 4 elems/thread.
// Also zeroes the loss accumulator (always runs before gather_loss).
__global__ void table_kernel(const float* __restrict__ adjacency) {
    size_t i4 = (size_t)blockIdx.x * blockDim.x + threadIdx.x;
    if (i4 == 0) g_loss_sum = 0.0;
    size_t base = i4 * 4;
    int k = (int)(base & (KCB - 1));         // multiple of 4; stays in-row
    float4 a = *reinterpret_cast<const float4*>(adjacency + base);
    float4 r;
    r.x = g_cnorm[k + 0] - 0.5f * (1.0f / (1.0f + __expf(-a.x)));
    r.y = g_cnorm[k + 1] - 0.5f * (1.0f / (1.0f + __expf(-a.y)));
    r.z = g_cnorm[k + 2] - 0.5f * (1.0f / (1.0f + __expf(-a.z)));
    r.w = g_cnorm[k + 3] - 0.5f * (1.0f / (1.0f + __expf(-a.w)));
    *reinterpret_cast<float4*>(g_table + base) = r;
}

// ---------------------------------------------------------------------------
// PTX helpers
__device__ __forceinline__ void cp_async16(uint32_t smem, const void* gmem) {
    asm volatile("cp.async.cg.shared.global [%0], [%1], 16;\n"
                 :: "r"(smem), "l"(gmem));
}
__device__ __forceinline__ void cp_commit() {
    asm volatile("cp.async.commit_group;\n");
}
__device__ __forceinline__ void cp_wait1() {
    asm volatile("cp.async.wait_group 1;\n" ::: "memory");
}
__device__ __forceinline__ void cp_wait0() {
    asm volatile("cp.async.wait_group 0;\n" ::: "memory");
}
__device__ __forceinline__ void ldsm4(uint32_t& r0, uint32_t& r1, uint32_t& r2,
                                      uint32_t& r3, uint32_t addr) {
    asm volatile("ldmatrix.sync.aligned.m8n8.x4.shared.b16 {%0,%1,%2,%3}, [%4];\n"
                 : "=r"(r0), "=r"(r1), "=r"(r2), "=r"(r3) : "r"(addr));
}

#define MMA_BF16(C, A0, A1, A2, A3, B0, B1)                                   \
    asm volatile(                                                             \
        "mma.sync.aligned.m16n8k16.row.col.f32.bf16.bf16.f32 "                \
        "{%0,%1,%2,%3}, {%4,%5,%6,%7}, {%8,%9}, {%0,%1,%2,%3};\n"             \
        : "+f"((C)[0]), "+f"((C)[1]), "+f"((C)[2]), "+f"((C)[3])              \
        : "r"(A0), "r"(A1), "r"(A2), "r"(A3), "r"(B0), "r"(B1))

// SW64 swizzle for 64-byte rows: XOR bits [5:4] with bits [8:7]
__device__ __forceinline__ uint32_t sw64(uint32_t off) {
    return off ^ ((off >> 3) & 0x30);
}

// ---------------------------------------------------------------------------
// Fused split-bf16 tensor-core distance GEMM + argmin.
// Block: 64 rows x (2048 cols in 16 passes of 128). 8 warps arranged 2(M)x4(N)
// -> warp tile 32x32. Per k16: 8 ldsm.x4 per 24 MMAs = 171 B/MMA (R13's 16x64
// tile was 213 B/MMA and pushed the CTA's smem demand to ~139 B/cyc at full
// tensor rate, over the 128 B/cyc crossbar -> tensor/L1 co-limited at ~65%).
// 32 acc regs/thread, ~80 regs total => 3 CTAs/SM (same occupancy as R13).
// A's DRAM re-read stays at 16 passes (2 GB). K=512 in 16 stages of 32,
// 3-stage cp.async ring, one sync/stage. k16=1 smem addresses derived from
// k16=0 by XOR 32 (NOT add - carry walks off the buffer; R11 crash).
#define KT       32
#define NSTAGE   3
#define A_B      (64 * 64)               // 4 KB per A matrix tile (64 x 32)
#define B_B      (128 * 64)              // 8 KB per B matrix tile (128 x 32)
#define STAGE_B  (2 * A_B + 2 * B_B)     // 24 KB
#define SMEM_TOT (NSTAGE * STAGE_B)      // 72 KB -> 3 CTAs in 228 KB

__device__ __forceinline__ void issue_stage(int row0, int n0, int k0,
                                            uint32_t sb) {
    const int tid = threadIdx.x;
    // A: zhi, zlo (64 rows x 32 cols = 256 16B-chunks each; 1 per thread)
    {
        const int row = tid >> 2, cc = tid & 3;
        const uint32_t so = sw64((uint32_t)(row * 64 + cc * 16));
        const size_t ga = (size_t)(row0 + row) * DIMF + k0 + cc * 8;
        cp_async16(sb + 0 * A_B + so, g_zhi + ga);
        cp_async16(sb + 1 * A_B + so, g_zlo + ga);
    }
    // B: chi, clo (128 rows x 32 cols = 512 chunks each; 2 per thread)
#pragma unroll
    for (int i = 0; i < 2; ++i) {
        const int c   = i * 256 + tid;
        const int row = c >> 2, cc = c & 3;
        const uint32_t so = sw64((uint32_t)(row * 64 + cc * 16));
        const size_t gb = (size_t)(n0 + row) * DIMF + k0 + cc * 8;
        cp_async16(sb + 2 * A_B + so,       g_chi + gb);
        cp_async16(sb + 2 * A_B + B_B + so, g_clo + gb);
    }
}

__global__ void __launch_bounds__(256, 3)
vq_argmin_mma_kernel(const int* __restrict__ prev_idx,
                     float*     __restrict__ idx_f32_out)
{
    extern __shared__ __align__(128) uint8_t dsm[];
    const uint32_t tiles = (uint32_t)__cvta_generic_to_shared(dsm);

    const int tid    = threadIdx.x;
    const int lane   = tid & 31;
    const int warp   = tid >> 5;
    const int warp_m = warp & 1;      // 2 warps along rows (32 each)
    const int warp_n = warp >> 1;     // 4 warps along cols (32 each)
    const int row0   = blockIdx.x * 64;

    // ldmatrix byte offsets for k16=0; k16=1 obtained by XOR 32
    uint32_t a_off[2];
#pragma unroll
    for (int im = 0; im < 2; ++im)
        a_off[im] = sw64((uint32_t)(
            (warp_m * 32 + im * 16 + (lane & 15)) * 64 + (lane >> 4) * 16));
    uint32_t b_off[2];
#pragma unroll
    for (int jp = 0; jp < 2; ++jp)
        b_off[jp] = sw64((uint32_t)(
            (warp_n * 32 + jp * 16 + (lane >> 4) * 8 + (lane & 7)) * 64 +
            ((lane & 8) ? 16 : 0)));

    // prev-symbol rows owned by this thread (pass-invariant)
    const int q = lane >> 2;
    int prevA[2], prevB[2];
#pragma unroll
    for (int im = 0; im < 2; ++im) {
        prevA[im] = prev_idx[row0 + warp_m * 32 + im * 16 + q];
        prevB[im] = prev_idx[row0 + warp_m * 32 + im * 16 + q + 8];
    }
    const int j2 = (lane & 3) * 2;

    float bv[4];
    int   bi[4];
#pragma unroll
    for (int s = 0; s < 4; ++s) { bv[s] = 3.4e38f; bi[s] = 0; }

    for (int nt = 0; nt < KCB / 128; ++nt) {
        const int n0 = nt * 128;

        float acc[2][4][4];
#pragma unroll
        for (int im = 0; im < 2; ++im)
#pragma unroll
            for (int jn = 0; jn < 4; ++jn)
#pragma unroll
                for (int r = 0; r < 4; ++r) acc[im][jn][r] = 0.0f;

        // prologue: 2 stages in flight
        issue_stage(row0, n0, 0, tiles);
        cp_commit();
        issue_stage(row0, n0, KT, tiles + STAGE_B);
        cp_commit();

        for (int kt = 0; kt < DIMF / KT; ++kt) {
            if (kt == DIMF / KT - 1) cp_wait0(); else cp_wait1();
            __syncthreads();
            if (kt + 2 < DIMF / KT) {
                issue_stage(row0, n0, (kt + 2) * KT,
                            tiles + (uint32_t)((kt + 2) % NSTAGE) * STAGE_B);
                cp_commit();
            }

            const uint32_t sb = tiles + (uint32_t)(kt % NSTAGE) * STAGE_B;
#pragma unroll
            for (int k16 = 0; k16 < 2; ++k16) {
                const uint32_t kx = (uint32_t)(k16 * 32);   // XOR, not add
                uint32_t ah[2][4], al[2][4];
#pragma unroll
                for (int im = 0; im < 2; ++im) {
                    ldsm4(ah[im][0], ah[im][1], ah[im][2], ah[im][3],
                          sb + 0 * A_B + (a_off[im] ^ kx));
                    ldsm4(al[im][0], al[im][1], al[im][2], al[im][3],
                          sb + 1 * A_B + (a_off[im] ^ kx));
                }
#pragma unroll
                for (int jp = 0; jp < 2; ++jp) {
                    uint32_t bh0, bh1, bh2, bh3, bl0, bl1, bl2, bl3;
                    ldsm4(bh0, bh1, bh2, bh3,
                          sb + 2 * A_B + (b_off[jp] ^ kx));
                    ldsm4(bl0, bl1, bl2, bl3,
                          sb + 2 * A_B + B_B + (b_off[jp] ^ kx));
#pragma unroll
                    for (int im = 0; im < 2; ++im) {
                        float* c0 = acc[im][jp * 2];
                        float* c1 = acc[im][jp * 2 + 1];
                        MMA_BF16(c0, ah[im][0], ah[im][1], ah[im][2], ah[im][3], bh0, bh1);
                        MMA_BF16(c0, ah[im][0], ah[im][1], ah[im][2], ah[im][3], bl0, bl1);
                        MMA_BF16(c0, al[im][0], al[im][1], al[im][2], al[im][3], bh0, bh1);
                        MMA_BF16(c1, ah[im][0], ah[im][1], ah[im][2], ah[im][3], bh2, bh3);
                        MMA_BF16(c1, ah[im][0], ah[im][1], ah[im][2], ah[im][3], bl2, bl3);
                        MMA_BF16(c1, al[im][0], al[im][1], al[im][2], al[im][3], bh2, bh3);
                    }
                }
            }
        }
        // all warps done reading this pass's buffers before next prologue
        __syncthreads();

        // Epilogue: fold bias table, update running argmin
        const int ncol0 = n0 + warp_n * 32 + j2;
#pragma unroll
        for (int im = 0; im < 2; ++im) {
            const float* tA = g_table + (size_t)prevA[im] * KCB + ncol0;
            const float* tB = g_table + (size_t)prevB[im] * KCB + ncol0;
#pragma unroll
            for (int jn = 0; jn < 4; ++jn) {
                float2 ta = *reinterpret_cast<const float2*>(tA + jn * 8);
                float2 tb = *reinterpret_cast<const float2*>(tB + jn * 8);
                const int col = ncol0 + jn * 8;
                float s0 = ta.x - 2.0f * acc[im][jn][0];
                float s1 = ta.y - 2.0f * acc[im][jn][1];
                float s2 = tb.x - 2.0f * acc[im][jn][2];
                float s3 = tb.y - 2.0f * acc[im][jn][3];
                const int sl0 = im * 2, sl1 = im * 2 + 1;
                if (s0 < bv[sl0]) { bv[sl0] = s0; bi[sl0] = col; }
                if (s1 < bv[sl0]) { bv[sl0] = s1; bi[sl0] = col + 1; }
                if (s2 < bv[sl1]) { bv[sl1] = s2; bi[sl1] = col; }
                if (s3 < bv[sl1]) { bv[sl1] = s3; bi[sl1] = col + 1; }
            }
        }
    }

    // Quad (4-lane) reduction: lanes sharing q own the same rows
#pragma unroll
    for (int s = 0; s < 4; ++s) {
#pragma unroll
        for (int d = 1; d < 4; d <<= 1) {
            float ov = __shfl_xor_sync(0xffffffffu, bv[s], d);
            int   oi = __shfl_xor_sync(0xffffffffu, bi[s], d);
            if (ov < bv[s] || (ov == bv[s] && oi < bi[s])) { bv[s] = ov; bi[s] = oi; }
        }
    }

    // Cross-warp (4 warp_n columns) reduction via smem (reuse tile buffer)
    __syncthreads();
    float* sv = reinterpret_cast<float*>(dsm);            // [64][4]
    int*   si = reinterpret_cast<int*>(sv + 256);         // [64][4]
    if ((lane & 3) == 0) {
#pragma unroll
        for (int s = 0; s < 4; ++s) {
            const int im = s >> 1, h = s & 1;
            const int rl = warp_m * 32 + im * 16 + h * 8 + q;
            sv[rl * 4 + warp_n] = bv[s];
            si[rl * 4 + warp_n] = bi[s];
        }
    }
    __syncthreads();
    if (tid < 64) {
        float best_v = sv[tid * 4];
        int   best_i = si[tid * 4];
#pragma unroll
        for (int w = 1; w < 4; ++w) {
            float v = sv[tid * 4 + w];
            int   i = si[tid * 4 + w];
            if (v < best_v || (v == best_v && i < best_i)) { best_v = v; best_i = i; }
        }
        g_min_idx[row0 + tid]   = best_i;
        idx_f32_out[row0 + tid] = (float)best_i;
    }
}

// ---------------------------------------------------------------------------
__global__ void gather_loss_kernel(const float* __restrict__ z_real,
                                   const float* __restrict__ z_imag,
                                   const float* __restrict__ codebook,
                                   float* __restrict__ out_real,
                                   float* __restrict__ out_imag)
{
    const int t = threadIdx.x;
    float local = 0.0f;
    for (int p = blockIdx.x; p < NPOS; p += gridDim.x) {
        const int idx = g_min_idx[p];
        float4 c4 = *reinterpret_cast<const float4*>(
            codebook + (size_t)idx * DIMF + t * 4);
        float4 z4;
        if (t < 64)
            z4 = *reinterpret_cast<const float4*>(z_real + (size_t)p * DIMH + t * 4);
        else
            z4 = *reinterpret_cast<const float4*>(z_imag + (size_t)p * DIMH + (t - 64) * 4);
        float dx = c4.x - z4.x, dy = c4.y - z4.y;
        float dz = c4.z - z4.z, dw = c4.w - z4.w;
        local += dx * dx + dy * dy + dz * dz + dw * dw;
        if (t < 64)
            *reinterpret_cast<float4*>(out_real + (size_t)p * DIMH + t * 4) = c4;
        else
            *reinterpret_cast<float4*>(out_imag + (size_t)p * DIMH + (t - 64) * 4) = c4;
    }
    __shared__ float red[128];
    red[t] = local;
    __syncthreads();
    for (int st = 64; st > 0; st >>= 1) {
        if (t < st) red[t] += red[t + st];
        __syncthreads();
    }
    if (t == 0) atomicAdd(&g_loss_sum, (double)red[0]);
}

// ---------------------------------------------------------------------------
__global__ void finalize_kernel(float* __restrict__ out_loss) {
    out_loss[0] = (float)(1.25 * g_loss_sum / (double)((size_t)NPOS * DIMF));
}

// ---------------------------------------------------------------------------
extern "C" void kernel_launch(void* const* d_in, const int* in_sizes, int n_in,
                              void* d_out, int out_size)
{
    const float* z_real    = (const float*)d_in[0];
    const float* z_imag    = (const float*)d_in[1];
    const int*   prev_idx  = (const int*)  d_in[2];
    const float* codebook  = (const float*)d_in[3];
    const float* adjacency = (const float*)d_in[4];

    float* out      = (float*)d_out;
    float* out_real = out;
    float* out_imag = out + (size_t)NPOS * DIMH;
    float* out_loss = out + 2 * (size_t)NPOS * DIMH;
    float* out_idx  = out_loss + 1;

    cudaFuncSetAttribute(vq_argmin_mma_kernel,
                         cudaFuncAttributeMaxDynamicSharedMemorySize, SMEM_TOT);

    cnorm_split_kernel<<<KCB, 128>>>(codebook);
    convert_z_kernel<<<(NPOS * (DIMF / 8)) / 256, 256>>>(z_real, z_imag);
    table_kernel<<<((size_t)KCB * KCB / 4) / 256, 256>>>(adjacency);
    vq_argmin_mma_kernel<<<NPOS / 64, 256, SMEM_TOT>>>(prev_idx, out_idx);
    gather_loss_kernel<<<2048, 128>>>(z_real, z_imag, codebook, out_real, out_imag);
    finalize_kernel<<<1, 1>>>(out_loss);
}

// round 15
// speedup vs baseline: 1.2757x; 1.0673x over previous
#include <cuda_runtime.h>
#include <cuda_bf16.h>
#include <cstdint>

// Problem constants: B=32, S=2048, D=256, K=2048
#define NPOS   65536
#define DIMH   256
#define DIMF   512
#define KCB    2048

// ---------------------------------------------------------------------------
// Device scratch (static; no cudaMalloc anywhere)
__device__ __nv_bfloat16 g_zhi[(size_t)NPOS * DIMF];   // 64 MB
__device__ __nv_bfloat16 g_zlo[(size_t)NPOS * DIMF];   // 64 MB
__device__ __nv_bfloat16 g_chi[(size_t)KCB * DIMF];    // 2 MB
__device__ __nv_bfloat16 g_clo[(size_t)KCB * DIMF];    // 2 MB
__device__ float  g_cnorm[KCB];
__device__ float  g_table[(size_t)KCB * KCB];          // 16 MB
__device__ int    g_min_idx[NPOS];
__device__ double g_loss_sum;

// ---------------------------------------------------------------------------
__global__ void cnorm_split_kernel(const float* __restrict__ codebook) {
    const int k = blockIdx.x;
    const int t = threadIdx.x;   // 128 threads, each owns 4 elems
    float4 v = *reinterpret_cast<const float4*>(codebook + (size_t)k * DIMF + t * 4);
    float s = v.x * v.x + v.y * v.y + v.z * v.z + v.w * v.w;

    float e[4] = {v.x, v.y, v.z, v.w};
    __nv_bfloat16 hi[4], lo[4];
#pragma unroll
    for (int i = 0; i < 4; ++i) {
        hi[i] = __float2bfloat16(e[i]);
        lo[i] = __float2bfloat16(e[i] - __bfloat162float(hi[i]));
    }
    size_t base = (size_t)k * DIMF + t * 4;
    *reinterpret_cast<__nv_bfloat162*>(g_chi + base)     = __nv_bfloat162(hi[0], hi[1]);
    *reinterpret_cast<__nv_bfloat162*>(g_chi + base + 2) = __nv_bfloat162(hi[2], hi[3]);
    *reinterpret_cast<__nv_bfloat162*>(g_clo + base)     = __nv_bfloat162(lo[0], lo[1]);
    *reinterpret_cast<__nv_bfloat162*>(g_clo + base + 2) = __nv_bfloat162(lo[2], lo[3]);

    __shared__ float red[128];
    red[t] = s;
    __syncthreads();
    for (int st = 64; st > 0; st >>= 1) {
        if (t < st) red[t] += red[t + st];
        __syncthreads();
    }
    if (t == 0) g_cnorm[k] = red[0];
}

// ---------------------------------------------------------------------------
// Split z (concat real/imag) into bf16 hi/lo. 8 elems/thread, 16B stores.
__global__ void convert_z_kernel(const float* __restrict__ z_real,
                                 const float* __restrict__ z_imag) {
    size_t e8 = (size_t)blockIdx.x * blockDim.x + threadIdx.x;
    size_t e  = e8 * 8;                      // element index in (NPOS, 512)
    int row = (int)(e >> 9);
    int c   = (int)(e & 511);                // multiple of 8; never crosses 256
    const float* src = (c < DIMH)
        ? (z_real + (size_t)row * DIMH + c)
        : (z_imag + (size_t)row * DIMH + (c - DIMH));
    float4 v0 = *reinterpret_cast<const float4*>(src);
    float4 v1 = *reinterpret_cast<const float4*>(src + 4);
    float el[8] = {v0.x, v0.y, v0.z, v0.w, v1.x, v1.y, v1.z, v1.w};
    __nv_bfloat16 hi[8], lo[8];
#pragma unroll
    for (int i = 0; i < 8; ++i) {
        hi[i] = __float2bfloat16(el[i]);
        lo[i] = __float2bfloat16(el[i] - __bfloat162float(hi[i]));
    }
    union { __nv_bfloat162 h2[4]; uint4 u; } ph, pl;
#pragma unroll
    for (int i = 0; i < 4; ++i) {
        ph.h2[i] = __nv_bfloat162(hi[2 * i], hi[2 * i + 1]);
        pl.h2[i] = __nv_bfloat162(lo[2 * i], lo[2 * i + 1]);
    }
    *reinterpret_cast<uint4*>(g_zhi + e) = ph.u;
    *reinterpret_cast<uint4*>(g_zlo + e) = pl.u;
}

// ---------------------------------------------------------------------------
// table[p*K + k] = cnorm[k] - 0.5 * sigmoid(adjacency[p][k]); 4 elems/thread.
// Also zeroes the loss accumulator (always runs before gather_loss).
__global__ void table_kernel(const float* __restrict__ adjacency) {
    size_t i4 = (size_t)blockIdx.x * blockDim.x + threadIdx.x;
    if (i4 == 0) g_loss_sum = 0.0;
    size_t base = i4 * 4;
    int k = (int)(base & (KCB - 1));         // multiple of 4; stays in-row
    float4 a = *reinterpret_cast<const float4*>(adjacency + base);
    float4 r;
    r.x = g_cnorm[k + 0] - 0.5f * (1.0f / (1.0f + __expf(-a.x)));
    r.y = g_cnorm[k + 1] - 0.5f * (1.0f / (1.0f + __expf(-a.y)));
    r.z = g_cnorm[k + 2] - 0.5f * (1.0f / (1.0f + __expf(-a.z)));
    r.w = g_cnorm[k + 3] - 0.5f * (1.0f / (1.0f + __expf(-a.w)));
    *reinterpret_cast<float4*>(g_table + base) = r;
}

// ---------------------------------------------------------------------------
// PTX helpers
__device__ __forceinline__ void cp_async16(uint32_t smem, const void* gmem) {
    asm volatile("cp.async.cg.shared.global [%0], [%1], 16;\n"
                 :: "r"(smem), "l"(gmem));
}
__device__ __forceinline__ void cp_commit() {
    asm volatile("cp.async.commit_group;\n");
}
__device__ __forceinline__ void cp_wait1() {
    asm volatile("cp.async.wait_group 1;\n" ::: "memory");
}
__device__ __forceinline__ void cp_wait0() {
    asm volatile("cp.async.wait_group 0;\n" ::: "memory");
}
__device__ __forceinline__ void ldsm4(uint32_t& r0, uint32_t& r1, uint32_t& r2,
                                      uint32_t& r3, uint32_t addr) {
    asm volatile("ldmatrix.sync.aligned.m8n8.x4.shared.b16 {%0,%1,%2,%3}, [%4];\n"
                 : "=r"(r0), "=r"(r1), "=r"(r2), "=r"(r3) : "r"(addr));
}
__device__ __forceinline__ void prefetch_l1(const void* p) {
    asm volatile("prefetch.global.L1 [%0];" :: "l"(p));
}

#define MMA_BF16(C, A0, A1, A2, A3, B0, B1)                                   \
    asm volatile(                                                             \
        "mma.sync.aligned.m16n8k16.row.col.f32.bf16.bf16.f32 "                \
        "{%0,%1,%2,%3}, {%4,%5,%6,%7}, {%8,%9}, {%0,%1,%2,%3};\n"             \
        : "+f"((C)[0]), "+f"((C)[1]), "+f"((C)[2]), "+f"((C)[3])              \
        : "r"(A0), "r"(A1), "r"(A2), "r"(A3), "r"(B0), "r"(B1))

// SW64 swizzle for 64-byte rows: XOR bits [5:4] with bits [8:7]
__device__ __forceinline__ uint32_t sw64(uint32_t off) {
    return off ^ ((off >> 3) & 0x30);
}

// ---------------------------------------------------------------------------
// Fused split-bf16 tensor-core distance GEMM + argmin.
// Block: 64 rows x (2048 cols in 16 passes of 128). 8 warps arranged 2(M)x4(N)
// -> warp tile 32x32, 32 acc regs/thread, 3 CTAs/SM (occ 33%).
// SINGLE CHANGE vs R14: within each jp group the 12 MMAs are issued
// term-major across the 4 accumulators (hh x4, hl x4, lh x4) -> accumulator
// reuse distance 4 MMAs (~32 cyc) instead of 1 (~8 cyc) against the ~24-cyc
// HMMA RAW latency. Per-accumulator term order (hh, hl, lh) is preserved, so
// results are bit-identical. Also: L1-prefetch of epilogue table rows at
// pass start. k16=1 smem addresses derived from k16=0 by XOR 32 (NOT add).
#define KT       32
#define NSTAGE   3
#define A_B      (64 * 64)               // 4 KB per A matrix tile (64 x 32)
#define B_B      (128 * 64)              // 8 KB per B matrix tile (128 x 32)
#define STAGE_B  (2 * A_B + 2 * B_B)     // 24 KB
#define SMEM_TOT (NSTAGE * STAGE_B)      // 72 KB -> 3 CTAs in 228 KB

__device__ __forceinline__ void issue_stage(int row0, int n0, int k0,
                                            uint32_t sb) {
    const int tid = threadIdx.x;
    // A: zhi, zlo (64 rows x 32 cols = 256 16B-chunks each; 1 per thread)
    {
        const int row = tid >> 2, cc = tid & 3;
        const uint32_t so = sw64((uint32_t)(row * 64 + cc * 16));
        const size_t ga = (size_t)(row0 + row) * DIMF + k0 + cc * 8;
        cp_async16(sb + 0 * A_B + so, g_zhi + ga);
        cp_async16(sb + 1 * A_B + so, g_zlo + ga);
    }
    // B: chi, clo (128 rows x 32 cols = 512 chunks each; 2 per thread)
#pragma unroll
    for (int i = 0; i < 2; ++i) {
        const int c   = i * 256 + tid;
        const int row = c >> 2, cc = c & 3;
        const uint32_t so = sw64((uint32_t)(row * 64 + cc * 16));
        const size_t gb = (size_t)(n0 + row) * DIMF + k0 + cc * 8;
        cp_async16(sb + 2 * A_B + so,       g_chi + gb);
        cp_async16(sb + 2 * A_B + B_B + so, g_clo + gb);
    }
}

__global__ void __launch_bounds__(256, 3)
vq_argmin_mma_kernel(const int* __restrict__ prev_idx,
                     float*     __restrict__ idx_f32_out)
{
    extern __shared__ __align__(128) uint8_t dsm[];
    const uint32_t tiles = (uint32_t)__cvta_generic_to_shared(dsm);

    const int tid    = threadIdx.x;
    const int lane   = tid & 31;
    const int warp   = tid >> 5;
    const int warp_m = warp & 1;      // 2 warps along rows (32 each)
    const int warp_n = warp >> 1;     // 4 warps along cols (32 each)
    const int row0   = blockIdx.x * 64;

    // ldmatrix byte offsets for k16=0; k16=1 obtained by XOR 32
    uint32_t a_off[2];
#pragma unroll
    for (int im = 0; im < 2; ++im)
        a_off[im] = sw64((uint32_t)(
            (warp_m * 32 + im * 16 + (lane & 15)) * 64 + (lane >> 4) * 16));
    uint32_t b_off[2];
#pragma unroll
    for (int jp = 0; jp < 2; ++jp)
        b_off[jp] = sw64((uint32_t)(
            (warp_n * 32 + jp * 16 + (lane >> 4) * 8 + (lane & 7)) * 64 +
            ((lane & 8) ? 16 : 0)));

    // prev-symbol rows owned by this thread (pass-invariant)
    const int q = lane >> 2;
    int prevA[2], prevB[2];
#pragma unroll
    for (int im = 0; im < 2; ++im) {
        prevA[im] = prev_idx[row0 + warp_m * 32 + im * 16 + q];
        prevB[im] = prev_idx[row0 + warp_m * 32 + im * 16 + q + 8];
    }
    const int j2 = (lane & 3) * 2;

    float bv[4];
    int   bi[4];
#pragma unroll
    for (int s = 0; s < 4; ++s) { bv[s] = 3.4e38f; bi[s] = 0; }

    for (int nt = 0; nt < KCB / 128; ++nt) {
        const int n0 = nt * 128;

        // Prefetch this pass's epilogue table rows into L1 while MMAs run.
        {
            const int nc = n0 + warp_n * 32 + j2;
#pragma unroll
            for (int im = 0; im < 2; ++im) {
                prefetch_l1(g_table + (size_t)prevA[im] * KCB + nc);
                prefetch_l1(g_table + (size_t)prevB[im] * KCB + nc);
            }
        }

        float acc[2][4][4];
#pragma unroll
        for (int im = 0; im < 2; ++im)
#pragma unroll
            for (int jn = 0; jn < 4; ++jn)
#pragma unroll
                for (int r = 0; r < 4; ++r) acc[im][jn][r] = 0.0f;

        // prologue: 2 stages in flight
        issue_stage(row0, n0, 0, tiles);
        cp_commit();
        issue_stage(row0, n0, KT, tiles + STAGE_B);
        cp_commit();

        for (int kt = 0; kt < DIMF / KT; ++kt) {
            if (kt == DIMF / KT - 1) cp_wait0(); else cp_wait1();
            __syncthreads();
            if (kt + 2 < DIMF / KT) {
                issue_stage(row0, n0, (kt + 2) * KT,
                            tiles + (uint32_t)((kt + 2) % NSTAGE) * STAGE_B);
                cp_commit();
            }

            const uint32_t sb = tiles + (uint32_t)(kt % NSTAGE) * STAGE_B;
#pragma unroll
            for (int k16 = 0; k16 < 2; ++k16) {
                const uint32_t kx = (uint32_t)(k16 * 32);   // XOR, not add
                uint32_t ah[2][4], al[2][4];
#pragma unroll
                for (int im = 0; im < 2; ++im) {
                    ldsm4(ah[im][0], ah[im][1], ah[im][2], ah[im][3],
                          sb + 0 * A_B + (a_off[im] ^ kx));
                    ldsm4(al[im][0], al[im][1], al[im][2], al[im][3],
                          sb + 1 * A_B + (a_off[im] ^ kx));
                }
#pragma unroll
                for (int jp = 0; jp < 2; ++jp) {
                    uint32_t bh0, bh1, bh2, bh3, bl0, bl1, bl2, bl3;
                    ldsm4(bh0, bh1, bh2, bh3,
                          sb + 2 * A_B + (b_off[jp] ^ kx));
                    ldsm4(bl0, bl1, bl2, bl3,
                          sb + 2 * A_B + B_B + (b_off[jp] ^ kx));
                    float* c00 = acc[0][jp * 2];
                    float* c01 = acc[0][jp * 2 + 1];
                    float* c10 = acc[1][jp * 2];
                    float* c11 = acc[1][jp * 2 + 1];
                    // Term-major issue: accumulator reuse distance = 4 MMAs
                    // (per-acc term order hh -> hl -> lh preserved).
                    MMA_BF16(c00, ah[0][0], ah[0][1], ah[0][2], ah[0][3], bh0, bh1);
                    MMA_BF16(c10, ah[1][0], ah[1][1], ah[1][2], ah[1][3], bh0, bh1);
                    MMA_BF16(c01, ah[0][0], ah[0][1], ah[0][2], ah[0][3], bh2, bh3);
                    MMA_BF16(c11, ah[1][0], ah[1][1], ah[1][2], ah[1][3], bh2, bh3);
                    MMA_BF16(c00, ah[0][0], ah[0][1], ah[0][2], ah[0][3], bl0, bl1);
                    MMA_BF16(c10, ah[1][0], ah[1][1], ah[1][2], ah[1][3], bl0, bl1);
                    MMA_BF16(c01, ah[0][0], ah[0][1], ah[0][2], ah[0][3], bl2, bl3);
                    MMA_BF16(c11, ah[1][0], ah[1][1], ah[1][2], ah[1][3], bl2, bl3);
                    MMA_BF16(c00, al[0][0], al[0][1], al[0][2], al[0][3], bh0, bh1);
                    MMA_BF16(c10, al[1][0], al[1][1], al[1][2], al[1][3], bh0, bh1);
                    MMA_BF16(c01, al[0][0], al[0][1], al[0][2], al[0][3], bh2, bh3);
                    MMA_BF16(c11, al[1][0], al[1][1], al[1][2], al[1][3], bh2, bh3);
                }
            }
        }
        // all warps done reading this pass's buffers before next prologue
        __syncthreads();

        // Epilogue: fold bias table, update running argmin
        const int ncol0 = n0 + warp_n * 32 + j2;
#pragma unroll
        for (int im = 0; im < 2; ++im) {
            const float* tA = g_table + (size_t)prevA[im] * KCB + ncol0;
            const float* tB = g_table + (size_t)prevB[im] * KCB + ncol0;
#pragma unroll
            for (int jn = 0; jn < 4; ++jn) {
                float2 ta = *reinterpret_cast<const float2*>(tA + jn * 8);
                float2 tb = *reinterpret_cast<const float2*>(tB + jn * 8);
                const int col = ncol0 + jn * 8;
                float s0 = ta.x - 2.0f * acc[im][jn][0];
                float s1 = ta.y - 2.0f * acc[im][jn][1];
                float s2 = tb.x - 2.0f * acc[im][jn][2];
                float s3 = tb.y - 2.0f * acc[im][jn][3];
                const int sl0 = im * 2, sl1 = im * 2 + 1;
                if (s0 < bv[sl0]) { bv[sl0] = s0; bi[sl0] = col; }
                if (s1 < bv[sl0]) { bv[sl0] = s1; bi[sl0] = col + 1; }
                if (s2 < bv[sl1]) { bv[sl1] = s2; bi[sl1] = col; }
                if (s3 < bv[sl1]) { bv[sl1] = s3; bi[sl1] = col + 1; }
            }
        }
    }

    // Quad (4-lane) reduction: lanes sharing q own the same rows
#pragma unroll
    for (int s = 0; s < 4; ++s) {
#pragma unroll
        for (int d = 1; d < 4; d <<= 1) {
            float ov = __shfl_xor_sync(0xffffffffu, bv[s], d);
            int   oi = __shfl_xor_sync(0xffffffffu, bi[s], d);
            if (ov < bv[s] || (ov == bv[s] && oi < bi[s])) { bv[s] = ov; bi[s] = oi; }
        }
    }

    // Cross-warp (4 warp_n columns) reduction via smem (reuse tile buffer)
    __syncthreads();
    float* sv = reinterpret_cast<float*>(dsm);            // [64][4]
    int*   si = reinterpret_cast<int*>(sv + 256);         // [64][4]
    if ((lane & 3) == 0) {
#pragma unroll
        for (int s = 0; s < 4; ++s) {
            const int im = s >> 1, h = s & 1;
            const int rl = warp_m * 32 + im * 16 + h * 8 + q;
            sv[rl * 4 + warp_n] = bv[s];
            si[rl * 4 + warp_n] = bi[s];
        }
    }
    __syncthreads();
    if (tid < 64) {
        float best_v = sv[tid * 4];
        int   best_i = si[tid * 4];
#pragma unroll
        for (int w = 1; w < 4; ++w) {
            float v = sv[tid * 4 + w];
            int   i = si[tid * 4 + w];
            if (v < best_v || (v == best_v && i < best_i)) { best_v = v; best_i = i; }
        }
        g_min_idx[row0 + tid]   = best_i;
        idx_f32_out[row0 + tid] = (float)best_i;
    }
}

// ---------------------------------------------------------------------------
__global__ void gather_loss_kernel(const float* __restrict__ z_real,
                                   const float* __restrict__ z_imag,
                                   const float* __restrict__ codebook,
                                   float* __restrict__ out_real,
                                   float* __restrict__ out_imag)
{
    const int t = threadIdx.x;
    float local = 0.0f;
    for (int p = blockIdx.x; p < NPOS; p += gridDim.x) {
        const int idx = g_min_idx[p];
        float4 c4 = *reinterpret_cast<const float4*>(
            codebook + (size_t)idx * DIMF + t * 4);
        float4 z4;
        if (t < 64)
            z4 = *reinterpret_cast<const float4*>(z_real + (size_t)p * DIMH + t * 4);
        else
            z4 = *reinterpret_cast<const float4*>(z_imag + (size_t)p * DIMH + (t - 64) * 4);
        float dx = c4.x - z4.x, dy = c4.y - z4.y;
        float dz = c4.z - z4.z, dw = c4.w - z4.w;
        local += dx * dx + dy * dy + dz * dz + dw * dw;
        if (t < 64)
            *reinterpret_cast<float4*>(out_real + (size_t)p * DIMH + t * 4) = c4;
        else
            *reinterpret_cast<float4*>(out_imag + (size_t)p * DIMH + (t - 64) * 4) = c4;
    }
    __shared__ float red[128];
    red[t] = local;
    __syncthreads();
    for (int st = 64; st > 0; st >>= 1) {
        if (t < st) red[t] += red[t + st];
        __syncthreads();
    }
    if (t == 0) atomicAdd(&g_loss_sum, (double)red[0]);
}

// ---------------------------------------------------------------------------
__global__ void finalize_kernel(float* __restrict__ out_loss) {
    out_loss[0] = (float)(1.25 * g_loss_sum / (double)((size_t)NPOS * DIMF));
}

// ---------------------------------------------------------------------------
extern "C" void kernel_launch(void* const* d_in, const int* in_sizes, int n_in,
                              void* d_out, int out_size)
{
    const float* z_real    = (const float*)d_in[0];
    const float* z_imag    = (const float*)d_in[1];
    const int*   prev_idx  = (const int*)  d_in[2];
    const float* codebook  = (const float*)d_in[3];
    const float* adjacency = (const float*)d_in[4];

    float* out      = (float*)d_out;
    float* out_real = out;
    float* out_imag = out + (size_t)NPOS * DIMH;
    float* out_loss = out + 2 * (size_t)NPOS * DIMH;
    float* out_idx  = out_loss + 1;

    cudaFuncSetAttribute(vq_argmin_mma_kernel,
                         cudaFuncAttributeMaxDynamicSharedMemorySize, SMEM_TOT);

    cnorm_split_kernel<<<KCB, 128>>>(codebook);
    convert_z_kernel<<<(NPOS * (DIMF / 8)) / 256, 256>>>(z_real, z_imag);
    table_kernel<<<((size_t)KCB * KCB / 4) / 256, 256>>>(adjacency);
    vq_argmin_mma_kernel<<<NPOS / 64, 256, SMEM_TOT>>>(prev_idx, out_idx);
    gather_loss_kernel<<<2048, 128>>>(z_real, z_imag, codebook, out_real, out_imag);
    finalize_kernel<<<1, 1>>>(out_loss);
}

// round 16
// speedup vs baseline: 1.2866x; 1.0085x over previous
#include <cuda_runtime.h>
#include <cuda_bf16.h>
#include <cstdint>

// Problem constants: B=32, S=2048, D=256, K=2048
#define NPOS   65536
#define DIMH   256
#define DIMF   512
#define KCB    2048

// ---------------------------------------------------------------------------
// Device scratch (static; no cudaMalloc anywhere)
__device__ __nv_bfloat16 g_zhi[(size_t)NPOS * DIMF];   // 64 MB
__device__ __nv_bfloat16 g_zlo[(size_t)NPOS * DIMF];   // 64 MB
__device__ __nv_bfloat16 g_chi[(size_t)KCB * DIMF];    // 2 MB
__device__ __nv_bfloat16 g_clo[(size_t)KCB * DIMF];    // 2 MB
__device__ float  g_cnorm[KCB];
__device__ float  g_table[(size_t)KCB * KCB];          // 16 MB
__device__ int    g_min_idx[NPOS];
__device__ double g_loss_sum;

// ---------------------------------------------------------------------------
__global__ void cnorm_split_kernel(const float* __restrict__ codebook) {
    const int k = blockIdx.x;
    const int t = threadIdx.x;   // 128 threads, each owns 4 elems
    float4 v = *reinterpret_cast<const float4*>(codebook + (size_t)k * DIMF + t * 4);
    float s = v.x * v.x + v.y * v.y + v.z * v.z + v.w * v.w;

    float e[4] = {v.x, v.y, v.z, v.w};
    __nv_bfloat16 hi[4], lo[4];
#pragma unroll
    for (int i = 0; i < 4; ++i) {
        hi[i] = __float2bfloat16(e[i]);
        lo[i] = __float2bfloat16(e[i] - __bfloat162float(hi[i]));
    }
    size_t base = (size_t)k * DIMF + t * 4;
    *reinterpret_cast<__nv_bfloat162*>(g_chi + base)     = __nv_bfloat162(hi[0], hi[1]);
    *reinterpret_cast<__nv_bfloat162*>(g_chi + base + 2) = __nv_bfloat162(hi[2], hi[3]);
    *reinterpret_cast<__nv_bfloat162*>(g_clo + base)     = __nv_bfloat162(lo[0], lo[1]);
    *reinterpret_cast<__nv_bfloat162*>(g_clo + base + 2) = __nv_bfloat162(lo[2], lo[3]);

    __shared__ float red[128];
    red[t] = s;
    __syncthreads();
    for (int st = 64; st > 0; st >>= 1) {
        if (t < st) red[t] += red[t + st];
        __syncthreads();
    }
    if (t == 0) g_cnorm[k] = red[0];
}

// ---------------------------------------------------------------------------
// Split z (concat real/imag) into bf16 hi/lo. 8 elems/thread, 16B stores.
__global__ void convert_z_kernel(const float* __restrict__ z_real,
                                 const float* __restrict__ z_imag) {
    size_t e8 = (size_t)blockIdx.x * blockDim.x + threadIdx.x;
    size_t e  = e8 * 8;                      // element index in (NPOS, 512)
    int row = (int)(e >> 9);
    int c   = (int)(e & 511);                // multiple of 8; never crosses 256
    const float* src = (c < DIMH)
        ? (z_real + (size_t)row * DIMH + c)
        : (z_imag + (size_t)row * DIMH + (c - DIMH));
    float4 v0 = *reinterpret_cast<const float4*>(src);
    float4 v1 = *reinterpret_cast<const float4*>(src + 4);
    float el[8] = {v0.x, v0.y, v0.z, v0.w, v1.x, v1.y, v1.z, v1.w};
    __nv_bfloat16 hi[8], lo[8];
#pragma unroll
    for (int i = 0; i < 8; ++i) {
        hi[i] = __float2bfloat16(el[i]);
        lo[i] = __float2bfloat16(el[i] - __bfloat162float(hi[i]));
    }
    union { __nv_bfloat162 h2[4]; uint4 u; } ph, pl;
#pragma unroll
    for (int i = 0; i < 4; ++i) {
        ph.h2[i] = __nv_bfloat162(hi[2 * i], hi[2 * i + 1]);
        pl.h2[i] = __nv_bfloat162(lo[2 * i], lo[2 * i + 1]);
    }
    *reinterpret_cast<uint4*>(g_zhi + e) = ph.u;
    *reinterpret_cast<uint4*>(g_zlo + e) = pl.u;
}

// ---------------------------------------------------------------------------
// table[p*K + k] = cnorm[k] - 0.5 * sigmoid(adjacency[p][k]); 4 elems/thread.
// Also zeroes the loss accumulator (always runs before gather_loss).
__global__ void table_kernel(const float* __restrict__ adjacency) {
    size_t i4 = (size_t)blockIdx.x * blockDim.x + threadIdx.x;
    if (i4 == 0) g_loss_sum = 0.0;
    size_t base = i4 * 4;
    int k = (int)(base & (KCB - 1));         // multiple of 4; stays in-row
    float4 a = *reinterpret_cast<const float4*>(adjacency + base);
    float4 r;
    r.x = g_cnorm[k + 0] - 0.5f * (1.0f / (1.0f + __expf(-a.x)));
    r.y = g_cnorm[k + 1] - 0.5f * (1.0f / (1.0f + __expf(-a.y)));
    r.z = g_cnorm[k + 2] - 0.5f * (1.0f / (1.0f + __expf(-a.z)));
    r.w = g_cnorm[k + 3] - 0.5f * (1.0f / (1.0f + __expf(-a.w)));
    *reinterpret_cast<float4*>(g_table + base) = r;
}

// ---------------------------------------------------------------------------
// PTX helpers
__device__ __forceinline__ void cp_async16(uint32_t smem, const void* gmem) {
    asm volatile("cp.async.cg.shared.global [%0], [%1], 16;\n"
                 :: "r"(smem), "l"(gmem));
}
__device__ __forceinline__ void cp_commit() {
    asm volatile("cp.async.commit_group;\n");
}
__device__ __forceinline__ void cp_wait1() {
    asm volatile("cp.async.wait_group 1;\n" ::: "memory");
}
__device__ __forceinline__ void cp_wait0() {
    asm volatile("cp.async.wait_group 0;\n" ::: "memory");
}
__device__ __forceinline__ void ldsm4(uint32_t& r0, uint32_t& r1, uint32_t& r2,
                                      uint32_t& r3, uint32_t addr) {
    asm volatile("ldmatrix.sync.aligned.m8n8.x4.shared.b16 {%0,%1,%2,%3}, [%4];\n"
                 : "=r"(r0), "=r"(r1), "=r"(r2), "=r"(r3) : "r"(addr));
}
__device__ __forceinline__ void prefetch_l1(const void* p) {
    asm volatile("prefetch.global.L1 [%0];" :: "l"(p));
}

#define MMA_BF16(C, A0, A1, A2, A3, B0, B1)                                   \
    asm volatile(                                                             \
        "mma.sync.aligned.m16n8k16.row.col.f32.bf16.bf16.f32 "                \
        "{%0,%1,%2,%3}, {%4,%5,%6,%7}, {%8,%9}, {%0,%1,%2,%3};\n"             \
        : "+f"((C)[0]), "+f"((C)[1]), "+f"((C)[2]), "+f"((C)[3])              \
        : "r"(A0), "r"(A1), "r"(A2), "r"(A3), "r"(B0), "r"(B1))

// SW64 swizzle for 64-byte rows: XOR bits [5:4] with bits [8:7]
__device__ __forceinline__ uint32_t sw64(uint32_t off) {
    return off ^ ((off >> 3) & 0x30);
}

// ---------------------------------------------------------------------------
// Fused split-bf16 tensor-core distance GEMM + argmin.
// Block: 64 rows x (2048 cols in 16 passes of 128). 8 warps arranged 2(M)x4(N)
// -> warp tile 32x32, 32 acc regs/thread, 3 CTAs/SM (occ 33%).
// SINGLE CHANGE vs R15 (which validated the accumulator-RAW-chain theory:
// distance 1->4 gave tensor 66.5->71.7%): hoist ALL fragment loads per k16
// (A and both jp B groups) and issue the 24 MMAs term-major across all
// EIGHT accumulators -> reuse distance 8 MMAs (~64 cyc) >> HMMA RAW latency.
// Per-accumulator term order (hh, hl, lh) preserved -> bit-identical.
// k16=1 smem addresses derived from k16=0 by XOR 32 (NOT add).
#define KT       32
#define NSTAGE   3
#define A_B      (64 * 64)               // 4 KB per A matrix tile (64 x 32)
#define B_B      (128 * 64)              // 8 KB per B matrix tile (128 x 32)
#define STAGE_B  (2 * A_B + 2 * B_B)     // 24 KB
#define SMEM_TOT (NSTAGE * STAGE_B)      // 72 KB -> 3 CTAs in 228 KB

__device__ __forceinline__ void issue_stage(int row0, int n0, int k0,
                                            uint32_t sb) {
    const int tid = threadIdx.x;
    // A: zhi, zlo (64 rows x 32 cols = 256 16B-chunks each; 1 per thread)
    {
        const int row = tid >> 2, cc = tid & 3;
        const uint32_t so = sw64((uint32_t)(row * 64 + cc * 16));
        const size_t ga = (size_t)(row0 + row) * DIMF + k0 + cc * 8;
        cp_async16(sb + 0 * A_B + so, g_zhi + ga);
        cp_async16(sb + 1 * A_B + so, g_zlo + ga);
    }
    // B: chi, clo (128 rows x 32 cols = 512 chunks each; 2 per thread)
#pragma unroll
    for (int i = 0; i < 2; ++i) {
        const int c   = i * 256 + tid;
        const int row = c >> 2, cc = c & 3;
        const uint32_t so = sw64((uint32_t)(row * 64 + cc * 16));
        const size_t gb = (size_t)(n0 + row) * DIMF + k0 + cc * 8;
        cp_async16(sb + 2 * A_B + so,       g_chi + gb);
        cp_async16(sb + 2 * A_B + B_B + so, g_clo + gb);
    }
}

__global__ void __launch_bounds__(256, 3)
vq_argmin_mma_kernel(const int* __restrict__ prev_idx,
                     float*     __restrict__ idx_f32_out)
{
    extern __shared__ __align__(128) uint8_t dsm[];
    const uint32_t tiles = (uint32_t)__cvta_generic_to_shared(dsm);

    const int tid    = threadIdx.x;
    const int lane   = tid & 31;
    const int warp   = tid >> 5;
    const int warp_m = warp & 1;      // 2 warps along rows (32 each)
    const int warp_n = warp >> 1;     // 4 warps along cols (32 each)
    const int row0   = blockIdx.x * 64;

    // ldmatrix byte offsets for k16=0; k16=1 obtained by XOR 32
    uint32_t a_off[2];
#pragma unroll
    for (int im = 0; im < 2; ++im)
        a_off[im] = sw64((uint32_t)(
            (warp_m * 32 + im * 16 + (lane & 15)) * 64 + (lane >> 4) * 16));
    uint32_t b_off[2];
#pragma unroll
    for (int jp = 0; jp < 2; ++jp)
        b_off[jp] = sw64((uint32_t)(
            (warp_n * 32 + jp * 16 + (lane >> 4) * 8 + (lane & 7)) * 64 +
            ((lane & 8) ? 16 : 0)));

    // prev-symbol rows owned by this thread (pass-invariant)
    const int q = lane >> 2;
    int prevA[2], prevB[2];
#pragma unroll
    for (int im = 0; im < 2; ++im) {
        prevA[im] = prev_idx[row0 + warp_m * 32 + im * 16 + q];
        prevB[im] = prev_idx[row0 + warp_m * 32 + im * 16 + q + 8];
    }
    const int j2 = (lane & 3) * 2;

    float bv[4];
    int   bi[4];
#pragma unroll
    for (int s = 0; s < 4; ++s) { bv[s] = 3.4e38f; bi[s] = 0; }

    for (int nt = 0; nt < KCB / 128; ++nt) {
        const int n0 = nt * 128;

        // Prefetch this pass's epilogue table rows into L1 while MMAs run.
        {
            const int nc = n0 + warp_n * 32 + j2;
#pragma unroll
            for (int im = 0; im < 2; ++im) {
                prefetch_l1(g_table + (size_t)prevA[im] * KCB + nc);
                prefetch_l1(g_table + (size_t)prevB[im] * KCB + nc);
            }
        }

        float acc[2][4][4];
#pragma unroll
        for (int im = 0; im < 2; ++im)
#pragma unroll
            for (int jn = 0; jn < 4; ++jn)
#pragma unroll
                for (int r = 0; r < 4; ++r) acc[im][jn][r] = 0.0f;

        // prologue: 2 stages in flight
        issue_stage(row0, n0, 0, tiles);
        cp_commit();
        issue_stage(row0, n0, KT, tiles + STAGE_B);
        cp_commit();

        for (int kt = 0; kt < DIMF / KT; ++kt) {
            if (kt == DIMF / KT - 1) cp_wait0(); else cp_wait1();
            __syncthreads();
            if (kt + 2 < DIMF / KT) {
                issue_stage(row0, n0, (kt + 2) * KT,
                            tiles + (uint32_t)((kt + 2) % NSTAGE) * STAGE_B);
                cp_commit();
            }

            const uint32_t sb = tiles + (uint32_t)(kt % NSTAGE) * STAGE_B;
#pragma unroll
            for (int k16 = 0; k16 < 2; ++k16) {
                const uint32_t kx = (uint32_t)(k16 * 32);   // XOR, not add
                // Hoist ALL fragment loads: 4 A + 4 B ldsm.x4
                uint32_t ah[2][4], al[2][4], bh[2][4], bl[2][4];
#pragma unroll
                for (int im = 0; im < 2; ++im) {
                    ldsm4(ah[im][0], ah[im][1], ah[im][2], ah[im][3],
                          sb + 0 * A_B + (a_off[im] ^ kx));
                    ldsm4(al[im][0], al[im][1], al[im][2], al[im][3],
                          sb + 1 * A_B + (a_off[im] ^ kx));
                }
#pragma unroll
                for (int jp = 0; jp < 2; ++jp) {
                    ldsm4(bh[jp][0], bh[jp][1], bh[jp][2], bh[jp][3],
                          sb + 2 * A_B + (b_off[jp] ^ kx));
                    ldsm4(bl[jp][0], bl[jp][1], bl[jp][2], bl[jp][3],
                          sb + 2 * A_B + B_B + (b_off[jp] ^ kx));
                }
                // 24 MMAs term-major across ALL 8 accumulators:
                // reuse distance 8 (~64 cyc). Per-acc order hh -> hl -> lh.
#pragma unroll
                for (int jp = 0; jp < 2; ++jp) {
#pragma unroll
                    for (int im = 0; im < 2; ++im) {
                        MMA_BF16(acc[im][jp * 2],
                                 ah[im][0], ah[im][1], ah[im][2], ah[im][3],
                                 bh[jp][0], bh[jp][1]);
                        MMA_BF16(acc[im][jp * 2 + 1],
                                 ah[im][0], ah[im][1], ah[im][2], ah[im][3],
                                 bh[jp][2], bh[jp][3]);
                    }
                }
#pragma unroll
                for (int jp = 0; jp < 2; ++jp) {
#pragma unroll
                    for (int im = 0; im < 2; ++im) {
                        MMA_BF16(acc[im][jp * 2],
                                 ah[im][0], ah[im][1], ah[im][2], ah[im][3],
                                 bl[jp][0], bl[jp][1]);
                        MMA_BF16(acc[im][jp * 2 + 1],
                                 ah[im][0], ah[im][1], ah[im][2], ah[im][3],
                                 bl[jp][2], bl[jp][3]);
                    }
                }
#pragma unroll
                for (int jp = 0; jp < 2; ++jp) {
#pragma unroll
                    for (int im = 0; im < 2; ++im) {
                        MMA_BF16(acc[im][jp * 2],
                                 al[im][0], al[im][1], al[im][2], al[im][3],
                                 bh[jp][0], bh[jp][1]);
                        MMA_BF16(acc[im][jp * 2 + 1],
                                 al[im][0], al[im][1], al[im][2], al[im][3],
                                 bh[jp][2], bh[jp][3]);
                    }
                }
            }
        }
        // all warps done reading this pass's buffers before next prologue
        __syncthreads();

        // Epilogue: fold bias table, update running argmin
        const int ncol0 = n0 + warp_n * 32 + j2;
#pragma unroll
        for (int im = 0; im < 2; ++im) {
            const float* tA = g_table + (size_t)prevA[im] * KCB + ncol0;
            const float* tB = g_table + (size_t)prevB[im] * KCB + ncol0;
#pragma unroll
            for (int jn = 0; jn < 4; ++jn) {
                float2 ta = *reinterpret_cast<const float2*>(tA + jn * 8);
                float2 tb = *reinterpret_cast<const float2*>(tB + jn * 8);
                const int col = ncol0 + jn * 8;
                float s0 = ta.x - 2.0f * acc[im][jn][0];
                float s1 = ta.y - 2.0f * acc[im][jn][1];
                float s2 = tb.x - 2.0f * acc[im][jn][2];
                float s3 = tb.y - 2.0f * acc[im][jn][3];
                const int sl0 = im * 2, sl1 = im * 2 + 1;
                if (s0 < bv[sl0]) { bv[sl0] = s0; bi[sl0] = col; }
                if (s1 < bv[sl0]) { bv[sl0] = s1; bi[sl0] = col + 1; }
                if (s2 < bv[sl1]) { bv[sl1] = s2; bi[sl1] = col; }
                if (s3 < bv[sl1]) { bv[sl1] = s3; bi[sl1] = col + 1; }
            }
        }
    }

    // Quad (4-lane) reduction: lanes sharing q own the same rows
#pragma unroll
    for (int s = 0; s < 4; ++s) {
#pragma unroll
        for (int d = 1; d < 4; d <<= 1) {
            float ov = __shfl_xor_sync(0xffffffffu, bv[s], d);
            int   oi = __shfl_xor_sync(0xffffffffu, bi[s], d);
            if (ov < bv[s] || (ov == bv[s] && oi < bi[s])) { bv[s] = ov; bi[s] = oi; }
        }
    }

    // Cross-warp (4 warp_n columns) reduction via smem (reuse tile buffer)
    __syncthreads();
    float* sv = reinterpret_cast<float*>(dsm);            // [64][4]
    int*   si = reinterpret_cast<int*>(sv + 256);         // [64][4]
    if ((lane & 3) == 0) {
#pragma unroll
        for (int s = 0; s < 4; ++s) {
            const int im = s >> 1, h = s & 1;
            const int rl = warp_m * 32 + im * 16 + h * 8 + q;
            sv[rl * 4 + warp_n] = bv[s];
            si[rl * 4 + warp_n] = bi[s];
        }
    }
    __syncthreads();
    if (tid < 64) {
        float best_v = sv[tid * 4];
        int   best_i = si[tid * 4];
#pragma unroll
        for (int w = 1; w < 4; ++w) {
            float v = sv[tid * 4 + w];
            int   i = si[tid * 4 + w];
            if (v < best_v || (v == best_v && i < best_i)) { best_v = v; best_i = i; }
        }
        g_min_idx[row0 + tid]   = best_i;
        idx_f32_out[row0 + tid] = (float)best_i;
    }
}

// ---------------------------------------------------------------------------
__global__ void gather_loss_kernel(const float* __restrict__ z_real,
                                   const float* __restrict__ z_imag,
                                   const float* __restrict__ codebook,
                                   float* __restrict__ out_real,
                                   float* __restrict__ out_imag)
{
    const int t = threadIdx.x;
    float local = 0.0f;
    for (int p = blockIdx.x; p < NPOS; p += gridDim.x) {
        const int idx = g_min_idx[p];
        float4 c4 = *reinterpret_cast<const float4*>(
            codebook + (size_t)idx * DIMF + t * 4);
        float4 z4;
        if (t < 64)
            z4 = *reinterpret_cast<const float4*>(z_real + (size_t)p * DIMH + t * 4);
        else
            z4 = *reinterpret_cast<const float4*>(z_imag + (size_t)p * DIMH + (t - 64) * 4);
        float dx = c4.x - z4.x, dy = c4.y - z4.y;
        float dz = c4.z - z4.z, dw = c4.w - z4.w;
        local += dx * dx + dy * dy + dz * dz + dw * dw;
        if (t < 64)
            *reinterpret_cast<float4*>(out_real + (size_t)p * DIMH + t * 4) = c4;
        else
            *reinterpret_cast<float4*>(out_imag + (size_t)p * DIMH + (t - 64) * 4) = c4;
    }
    __shared__ float red[128];
    red[t] = local;
    __syncthreads();
    for (int st = 64; st > 0; st >>= 1) {
        if (t < st) red[t] += red[t + st];
        __syncthreads();
    }
    if (t == 0) atomicAdd(&g_loss_sum, (double)red[0]);
}

// ---------------------------------------------------------------------------
__global__ void finalize_kernel(float* __restrict__ out_loss) {
    out_loss[0] = (float)(1.25 * g_loss_sum / (double)((size_t)NPOS * DIMF));
}

// ---------------------------------------------------------------------------
extern "C" void kernel_launch(void* const* d_in, const int* in_sizes, int n_in,
                              void* d_out, int out_size)
{
    const float* z_real    = (const float*)d_in[0];
    const float* z_imag    = (const float*)d_in[1];
    const int*   prev_idx  = (const int*)  d_in[2];
    const float* codebook  = (const float*)d_in[3];
    const float* adjacency = (const float*)d_in[4];

    float* out      = (float*)d_out;
    float* out_real = out;
    float* out_imag = out + (size_t)NPOS * DIMH;
    float* out_loss = out + 2 * (size_t)NPOS * DIMH;
    float* out_idx  = out_loss + 1;

    cudaFuncSetAttribute(vq_argmin_mma_kernel,
                         cudaFuncAttributeMaxDynamicSharedMemorySize, SMEM_TOT);

    cnorm_split_kernel<<<KCB, 128>>>(codebook);
    convert_z_kernel<<<(NPOS * (DIMF / 8)) / 256, 256>>>(z_real, z_imag);
    table_kernel<<<((size_t)KCB * KCB / 4) / 256, 256>>>(adjacency);
    vq_argmin_mma_kernel<<<NPOS / 64, 256, SMEM_TOT>>>(prev_idx, out_idx);
    gather_loss_kernel<<<2048, 128>>>(z_real, z_imag, codebook, out_real, out_imag);
    finalize_kernel<<<1, 1>>>(out_loss);
}